// round 1
// baseline (speedup 1.0000x reference)
#include <cuda_runtime.h>

#define Bb 2
#define Tt 2048
#define Cc 1024
#define Hh 16
#define Dd 64
#define Mm (Bb*Tt)

__device__ float g_q[Bb*Hh*Tt*Dd];
__device__ float g_k[Bb*Hh*Tt*Dd];
__device__ float g_v[Bb*Hh*Tt*Dd];
__device__ float g_ctx[Mm*Cc];

__global__ __launch_bounds__(256) void qkv_gemm(
    const float* __restrict__ A,
    const float* __restrict__ Wq, const float* __restrict__ bq,
    const float* __restrict__ Wk, const float* __restrict__ bk,
    const float* __restrict__ Wv, const float* __restrict__ bv)
{
    const int bm   = blockIdx.y * 128;
    const int bn_g = blockIdx.x * 128;
    const int which = bn_g >> 10;
    const int bn   = bn_g & 1023;
    const float* W    = (which == 0) ? Wq : (which == 1) ? Wk : Wv;
    const float* bias = (which == 0) ? bq : (which == 1) ? bk : bv;
    float* out        = (which == 0) ? g_q : (which == 1) ? g_k : g_v;

    __shared__ float As[8][128];
    __shared__ float Bs[8][128];

    const int tid  = threadIdx.x;
    const int tr   = tid >> 4;
    const int tc   = tid & 15;
    const int aRow = tid >> 1;
    const int aCol = (tid & 1) << 2;
    const int bRow = tid >> 5;
    const int bCol = (tid & 31) << 2;

    const float* Ap = A + (size_t)(bm + aRow) * Cc + aCol;
    const float* Wp = W + (size_t)bRow * Cc + bn + bCol;

    float acc[8][8];
#pragma unroll
    for (int i = 0; i < 8; i++)
#pragma unroll
        for (int j = 0; j < 8; j++) acc[i][j] = 0.f;

    for (int k0 = 0; k0 < Cc; k0 += 8) {
        float4 av = *(const float4*)(Ap + k0);
        As[aCol + 0][aRow] = av.x;
        As[aCol + 1][aRow] = av.y;
        As[aCol + 2][aRow] = av.z;
        As[aCol + 3][aRow] = av.w;
        float4 wv = *(const float4*)(Wp + (size_t)k0 * Cc);
        *(float4*)&Bs[bRow][bCol] = wv;
        __syncthreads();
#pragma unroll
        for (int kk = 0; kk < 8; kk++) {
            float ra[8], rb[8];
            *(float4*)(ra)     = *(const float4*)&As[kk][tr * 8];
            *(float4*)(ra + 4) = *(const float4*)&As[kk][tr * 8 + 4];
            *(float4*)(rb)     = *(const float4*)&Bs[kk][tc * 8];
            *(float4*)(rb + 4) = *(const float4*)&Bs[kk][tc * 8 + 4];
#pragma unroll
            for (int i = 0; i < 8; i++)
#pragma unroll
                for (int j = 0; j < 8; j++)
                    acc[i][j] = fmaf(ra[i], rb[j], acc[i][j]);
        }
        __syncthreads();
    }

#pragma unroll
    for (int i = 0; i < 8; i++) {
        const int m = bm + tr * 8 + i;
        const int b = m >> 11, t = m & 2047;
#pragma unroll
        for (int j = 0; j < 8; j++) {
            const int c = bn + tc * 8 + j;
            const int h = c >> 6, d = c & 63;
            out[(((size_t)(b * Hh + h) * Tt) + t) * Dd + d] = acc[i][j] + bias[c];
        }
    }
}

__global__ __launch_bounds__(256) void out_gemm(
    const float* __restrict__ Wo, const float* __restrict__ bo,
    float* __restrict__ out)
{
    const int bm = blockIdx.y * 128;
    const int bn = blockIdx.x * 128;

    __shared__ float As[8][128];
    __shared__ float Bs[8][128];

    const int tid  = threadIdx.x;
    const int tr   = tid >> 4;
    const int tc   = tid & 15;
    const int aRow = tid >> 1;
    const int aCol = (tid & 1) << 2;
    const int bRow = tid >> 5;
    const int bCol = (tid & 31) << 2;

    const float* Ap = g_ctx + (size_t)(bm + aRow) * Cc + aCol;
    const float* Wp = Wo + (size_t)bRow * Cc + bn + bCol;

    float acc[8][8];
#pragma unroll
    for (int i = 0; i < 8; i++)
#pragma unroll
        for (int j = 0; j < 8; j++) acc[i][j] = 0.f;

    for (int k0 = 0; k0 < Cc; k0 += 8) {
        float4 av = *(const float4*)(Ap + k0);
        As[aCol + 0][aRow] = av.x;
        As[aCol + 1][aRow] = av.y;
        As[aCol + 2][aRow] = av.z;
        As[aCol + 3][aRow] = av.w;
        float4 wv = *(const float4*)(Wp + (size_t)k0 * Cc);
        *(float4*)&Bs[bRow][bCol] = wv;
        __syncthreads();
#pragma unroll
        for (int kk = 0; kk < 8; kk++) {
            float ra[8], rb[8];
            *(float4*)(ra)     = *(const float4*)&As[kk][tr * 8];
            *(float4*)(ra + 4) = *(const float4*)&As[kk][tr * 8 + 4];
            *(float4*)(rb)     = *(const float4*)&Bs[kk][tc * 8];
            *(float4*)(rb + 4) = *(const float4*)&Bs[kk][tc * 8 + 4];
#pragma unroll
            for (int i = 0; i < 8; i++)
#pragma unroll
                for (int j = 0; j < 8; j++)
                    acc[i][j] = fmaf(ra[i], rb[j], acc[i][j]);
        }
        __syncthreads();
    }

#pragma unroll
    for (int i = 0; i < 8; i++) {
        const int m = bm + tr * 8 + i;
#pragma unroll
        for (int j = 0; j < 8; j++) {
            const int c = bn + tc * 8 + j;
            out[(size_t)m * Cc + c] = acc[i][j] + bo[c];
        }
    }
}

__global__ __launch_bounds__(256) void attn_kernel()
{
    __shared__ float Qt[64 * 64];
    __shared__ float KtPs[64 * 64];
    __shared__ float Vs[64 * 64];

    const int bh  = blockIdx.y;
    const int qb  = blockIdx.x;
    const int tid = threadIdx.x;
    const int ty  = tid >> 4, tx = tid & 15;

    const float* qp = g_q + (size_t)bh * Tt * Dd;
    const float* kp = g_k + (size_t)bh * Tt * Dd;
    const float* vp = g_v + (size_t)bh * Tt * Dd;

    {
        const int t  = tid >> 2;
        const int d0 = (tid & 3) << 4;
        const float* src = qp + (size_t)(qb * 64 + t) * Dd + d0;
#pragma unroll
        for (int u = 0; u < 16; u += 4) {
            float4 qv = *(const float4*)(src + u);
            Qt[(d0 + u + 0) * 64 + t] = qv.x * 0.125f;
            Qt[(d0 + u + 1) * 64 + t] = qv.y * 0.125f;
            Qt[(d0 + u + 2) * 64 + t] = qv.z * 0.125f;
            Qt[(d0 + u + 3) * 64 + t] = qv.w * 0.125f;
        }
    }

    float m_i[4], l_i[4], O[4][4];
#pragma unroll
    for (int i = 0; i < 4; i++) {
        m_i[i] = -1e30f; l_i[i] = 0.f;
#pragma unroll
        for (int j = 0; j < 4; j++) O[i][j] = 0.f;
    }

    for (int kb = 0; kb <= qb; kb++) {
        __syncthreads();
        {
            const int t  = tid >> 2;
            const int d0 = (tid & 3) << 4;
            const float* ks = kp + (size_t)(kb * 64 + t) * Dd + d0;
            const float* vs = vp + (size_t)(kb * 64 + t) * Dd + d0;
#pragma unroll
            for (int u = 0; u < 16; u += 4) {
                float4 kv = *(const float4*)(ks + u);
                KtPs[(d0 + u + 0) * 64 + t] = kv.x;
                KtPs[(d0 + u + 1) * 64 + t] = kv.y;
                KtPs[(d0 + u + 2) * 64 + t] = kv.z;
                KtPs[(d0 + u + 3) * 64 + t] = kv.w;
                *(float4*)&Vs[t * 64 + d0 + u] = *(const float4*)(vs + u);
            }
        }
        __syncthreads();

        float s[4][4];
#pragma unroll
        for (int i = 0; i < 4; i++)
#pragma unroll
            for (int j = 0; j < 4; j++) s[i][j] = 0.f;

#pragma unroll 8
        for (int d = 0; d < 64; d++) {
            float4 qv = *(const float4*)&Qt[d * 64 + ty * 4];
            float4 kv = *(const float4*)&KtPs[d * 64 + tx * 4];
            const float qa[4] = {qv.x, qv.y, qv.z, qv.w};
            const float ka[4] = {kv.x, kv.y, kv.z, kv.w};
#pragma unroll
            for (int i = 0; i < 4; i++)
#pragma unroll
                for (int j = 0; j < 4; j++)
                    s[i][j] = fmaf(qa[i], ka[j], s[i][j]);
        }

        if (kb == qb) {
#pragma unroll
            for (int i = 0; i < 4; i++)
#pragma unroll
                for (int j = 0; j < 4; j++)
                    if (tx * 4 + j > ty * 4 + i) s[i][j] = -1e30f;
        }

        float pr[4][4];
#pragma unroll
        for (int i = 0; i < 4; i++) {
            float mx = fmaxf(fmaxf(s[i][0], s[i][1]), fmaxf(s[i][2], s[i][3]));
#pragma unroll
            for (int off = 8; off; off >>= 1)
                mx = fmaxf(mx, __shfl_xor_sync(0xffffffffu, mx, off));
            const float mn = fmaxf(m_i[i], mx);
            const float corr = __expf(m_i[i] - mn);
            m_i[i] = mn;
            float ssum = 0.f;
#pragma unroll
            for (int j = 0; j < 4; j++) {
                pr[i][j] = __expf(s[i][j] - mn);
                ssum += pr[i][j];
            }
#pragma unroll
            for (int off = 8; off; off >>= 1)
                ssum += __shfl_xor_sync(0xffffffffu, ssum, off);
            l_i[i] = l_i[i] * corr + ssum;
#pragma unroll
            for (int j = 0; j < 4; j++) O[i][j] *= corr;
        }

        __syncthreads();
#pragma unroll
        for (int i = 0; i < 4; i++)
            *(float4*)&KtPs[(ty * 4 + i) * 64 + tx * 4] =
                make_float4(pr[i][0], pr[i][1], pr[i][2], pr[i][3]);
        __syncthreads();

#pragma unroll 8
        for (int kk = 0; kk < 64; kk++) {
            float4 vv = *(const float4*)&Vs[kk * 64 + tx * 4];
#pragma unroll
            for (int i = 0; i < 4; i++) {
                const float p = KtPs[(ty * 4 + i) * 64 + kk];
                O[i][0] = fmaf(p, vv.x, O[i][0]);
                O[i][1] = fmaf(p, vv.y, O[i][1]);
                O[i][2] = fmaf(p, vv.z, O[i][2]);
                O[i][3] = fmaf(p, vv.w, O[i][3]);
            }
        }
    }

    const int b = bh >> 4, h = bh & 15;
#pragma unroll
    for (int i = 0; i < 4; i++) {
        const float inv = 1.f / l_i[i];
        const int t = qb * 64 + ty * 4 + i;
        float* dst = g_ctx + ((size_t)(b * Tt + t)) * Cc + h * Dd + tx * 4;
        *(float4*)dst = make_float4(O[i][0] * inv, O[i][1] * inv,
                                    O[i][2] * inv, O[i][3] * inv);
    }
}

extern "C" void kernel_launch(void* const* d_in, const int* in_sizes, int n_in,
                              void* d_out, int out_size)
{
    (void)in_sizes; (void)n_in; (void)out_size;
    const float* hs = (const float*)d_in[0];
    const float* Wq = (const float*)d_in[2];
    const float* bq = (const float*)d_in[3];
    const float* Wk = (const float*)d_in[4];
    const float* bk = (const float*)d_in[5];
    const float* Wv = (const float*)d_in[6];
    const float* bv = (const float*)d_in[7];
    const float* Wo = (const float*)d_in[8];
    const float* bo = (const float*)d_in[9];

    qkv_gemm<<<dim3(24, 32), 256>>>(hs, Wq, bq, Wk, bk, Wv, bv);
    attn_kernel<<<dim3(32, 32), 256>>>();
    out_gemm<<<dim3(8, 32), 256>>>(Wo, bo, (float*)d_out);
}

// round 3
// speedup vs baseline: 2.4076x; 2.4076x over previous
#include <cuda_runtime.h>
#include <cuda_bf16.h>
#include <cstdint>

#define Tt 2048
#define Cc 1024
#define Hh 16
#define Mm 4096
#define MB1 (1024*1024)
#define GP 72   // padded smem row stride (elements); 144B = 9*16 keeps uint4 alignment

// ---------------- static device scratch ----------------
__device__ __nv_bfloat16 g_ahi[Mm*Cc], g_alo[Mm*Cc];     // hidden_states split
__device__ __nv_bfloat16 g_qhi[Mm*Cc], g_qlo[Mm*Cc];     // [B*H, T, 64], pre-scaled
__device__ __nv_bfloat16 g_khi[Mm*Cc], g_klo[Mm*Cc];
__device__ __nv_bfloat16 g_vhi[Mm*Cc], g_vlo[Mm*Cc];
__device__ __nv_bfloat16 g_chi[Mm*Cc], g_clo[Mm*Cc];     // ctx split [M, C]
__device__ __nv_bfloat16 g_wt_hi[3*MB1], g_wt_lo[3*MB1]; // Wq^T|Wk^T|Wv^T [N,K]
__device__ __nv_bfloat16 g_wo_hi[MB1],  g_wo_lo[MB1];    // Wo^T [N,K]

// ---------------- helpers ----------------
__device__ __forceinline__ void mma_bf16(float c[4], const uint32_t a[4], const uint32_t b[2]) {
    asm volatile(
        "mma.sync.aligned.m16n8k16.row.col.f32.bf16.bf16.f32 "
        "{%0,%1,%2,%3}, {%4,%5,%6,%7}, {%8,%9}, {%0,%1,%2,%3};"
        : "+f"(c[0]), "+f"(c[1]), "+f"(c[2]), "+f"(c[3])
        : "r"(a[0]), "r"(a[1]), "r"(a[2]), "r"(a[3]), "r"(b[0]), "r"(b[1]));
}
__device__ __forceinline__ uint32_t pack2(float x, float y) {
    __nv_bfloat162 t;
    t.x = __float2bfloat16(x);
    t.y = __float2bfloat16(y);
    return *(uint32_t*)&t;
}
__device__ __forceinline__ float bres(float x) {
    return x - __bfloat162float(__float2bfloat16(x));
}
__device__ __forceinline__ void split_store(__nv_bfloat16* hi, __nv_bfloat16* lo,
                                            size_t idx, float a, float b) {
    __nv_bfloat16 ha = __float2bfloat16(a), hb = __float2bfloat16(b);
    __nv_bfloat162 hv; hv.x = ha; hv.y = hb;
    *(__nv_bfloat162*)&hi[idx] = hv;
    __nv_bfloat162 lv;
    lv.x = __float2bfloat16(a - __bfloat162float(ha));
    lv.y = __float2bfloat16(b - __bfloat162float(hb));
    *(__nv_bfloat162*)&lo[idx] = lv;
}

// ---------------- split kernels ----------------
__global__ __launch_bounds__(256) void split_hs(const float* __restrict__ src)
{
    size_t i0 = ((size_t)blockIdx.x * 256 + threadIdx.x) * 4;
    float4 x = *(const float4*)(src + i0);
    float xs[4] = {x.x, x.y, x.z, x.w};
#pragma unroll
    for (int j = 0; j < 4; j++) {
        __nv_bfloat16 h = __float2bfloat16(xs[j]);
        g_ahi[i0 + j] = h;
        g_alo[i0 + j] = __float2bfloat16(xs[j] - __bfloat162float(h));
    }
}

__global__ __launch_bounds__(256) void wsplit(const float* __restrict__ W, int widx)
{
    __shared__ float tile[32][33];
    __nv_bfloat16* hi = (widx < 3) ? (g_wt_hi + (size_t)widx * MB1) : g_wo_hi;
    __nv_bfloat16* lo = (widx < 3) ? (g_wt_lo + (size_t)widx * MB1) : g_wo_lo;
    const int tx = threadIdx.x & 31, ty0 = threadIdx.x >> 5;
    const int n0 = blockIdx.x * 32, k0 = blockIdx.y * 32;
#pragma unroll
    for (int r = ty0; r < 32; r += 8)
        tile[r][tx] = W[(size_t)(k0 + r) * Cc + n0 + tx];
    __syncthreads();
#pragma unroll
    for (int r = ty0; r < 32; r += 8) {
        float xv = tile[tx][r];  // W[k0+tx][n0+r]
        __nv_bfloat16 h = __float2bfloat16(xv);
        hi[(size_t)(n0 + r) * Cc + k0 + tx] = h;
        lo[(size_t)(n0 + r) * Cc + k0 + tx] = __float2bfloat16(xv - __bfloat162float(h));
    }
}

// ---------------- split-bf16 mma GEMM ----------------
// mode 0: A = hs split, B = QKV weights; epilogue -> split q/k/v [B*H,T,D] (q scaled)
// mode 1: A = ctx split, B = Wo; epilogue -> fp32 d_out
__global__ __launch_bounds__(256) void mma_gemm(
    const float* __restrict__ bias0, const float* __restrict__ bias1,
    const float* __restrict__ bias2, float* __restrict__ outPlain, int mode)
{
    extern __shared__ __align__(16) char smem_raw[];
    __nv_bfloat16* s = (__nv_bfloat16*)smem_raw;
    __nv_bfloat16 *sAhi = s, *sAlo = s + 9216, *sBhi = s + 18432, *sBlo = s + 27648;

    const int tid = threadIdx.x, lane = tid & 31, wid = tid >> 5;
    const int wm = wid >> 2, wn = wid & 3;
    const int g = lane >> 2, tq = lane & 3;
    const int m0 = blockIdx.y * 128, n_g = blockIdx.x * 128;

    const __nv_bfloat16* Ahi = (mode == 0) ? g_ahi : g_chi;
    const __nv_bfloat16* Alo = (mode == 0) ? g_alo : g_clo;
    const __nv_bfloat16* Bhi = (mode == 0) ? g_wt_hi : g_wo_hi;
    const __nv_bfloat16* Blo = (mode == 0) ? g_wt_lo : g_wo_lo;

    float acc[4][4][4];
#pragma unroll
    for (int i = 0; i < 4; i++)
#pragma unroll
        for (int j = 0; j < 4; j++)
#pragma unroll
            for (int r = 0; r < 4; r++) acc[i][j][r] = 0.f;

    const int lrow = tid >> 1, lseg = (tid & 1) * 32;

    for (int ch = 0; ch < 16; ch++) {
        const int k0 = ch * 64;
        const __nv_bfloat16* pah = Ahi + (size_t)(m0 + lrow) * Cc + k0 + lseg;
        const __nv_bfloat16* pal = Alo + (size_t)(m0 + lrow) * Cc + k0 + lseg;
        const __nv_bfloat16* pbh = Bhi + (size_t)(n_g + lrow) * Cc + k0 + lseg;
        const __nv_bfloat16* pbl = Blo + (size_t)(n_g + lrow) * Cc + k0 + lseg;
#pragma unroll
        for (int i = 0; i < 4; i++) {
            *(uint4*)&sAhi[lrow * GP + lseg + i * 8] = *(const uint4*)(pah + i * 8);
            *(uint4*)&sAlo[lrow * GP + lseg + i * 8] = *(const uint4*)(pal + i * 8);
            *(uint4*)&sBhi[lrow * GP + lseg + i * 8] = *(const uint4*)(pbh + i * 8);
            *(uint4*)&sBlo[lrow * GP + lseg + i * 8] = *(const uint4*)(pbl + i * 8);
        }
        __syncthreads();

#pragma unroll
        for (int ks = 0; ks < 4; ks++) {
            const int tk = ks * 16 + tq * 2;
            uint32_t ahi[4][4], alo[4][4];
#pragma unroll
            for (int mt = 0; mt < 4; mt++) {
                const int r = wm * 64 + mt * 16 + g;
                ahi[mt][0] = *(const uint32_t*)&sAhi[r * GP + tk];
                ahi[mt][1] = *(const uint32_t*)&sAhi[(r + 8) * GP + tk];
                ahi[mt][2] = *(const uint32_t*)&sAhi[r * GP + tk + 8];
                ahi[mt][3] = *(const uint32_t*)&sAhi[(r + 8) * GP + tk + 8];
                alo[mt][0] = *(const uint32_t*)&sAlo[r * GP + tk];
                alo[mt][1] = *(const uint32_t*)&sAlo[(r + 8) * GP + tk];
                alo[mt][2] = *(const uint32_t*)&sAlo[r * GP + tk + 8];
                alo[mt][3] = *(const uint32_t*)&sAlo[(r + 8) * GP + tk + 8];
            }
#pragma unroll
            for (int nt = 0; nt < 4; nt++) {
                const int cb = wn * 32 + nt * 8 + g;
                uint32_t bhi[2] = {*(const uint32_t*)&sBhi[cb * GP + tk],
                                   *(const uint32_t*)&sBhi[cb * GP + tk + 8]};
                uint32_t blo[2] = {*(const uint32_t*)&sBlo[cb * GP + tk],
                                   *(const uint32_t*)&sBlo[cb * GP + tk + 8]};
#pragma unroll
                for (int mt = 0; mt < 4; mt++) {
                    mma_bf16(acc[mt][nt], ahi[mt], bhi);
                    mma_bf16(acc[mt][nt], ahi[mt], blo);
                    mma_bf16(acc[mt][nt], alo[mt], bhi);
                }
            }
        }
        __syncthreads();
    }

    if (mode == 0) {
        const int which = n_g >> 10;
        const int nloc = n_g & 1023;
        const float* bias = (which == 0) ? bias0 : (which == 1) ? bias1 : bias2;
        __nv_bfloat16* ohi = (which == 0) ? g_qhi : (which == 1) ? g_khi : g_vhi;
        __nv_bfloat16* olo = (which == 0) ? g_qlo : (which == 1) ? g_klo : g_vlo;
        const float scale = (which == 0) ? 0.125f : 1.0f;
#pragma unroll
        for (int mt = 0; mt < 4; mt++) {
            const int r0 = m0 + wm * 64 + mt * 16 + g;
            const int r1 = r0 + 8;
            const int b0i = r0 >> 11, t0 = r0 & 2047;
            const int b1i = r1 >> 11, t1 = r1 & 2047;
#pragma unroll
            for (int nt = 0; nt < 4; nt++) {
                const int c = nloc + wn * 32 + nt * 8 + tq * 2;
                const int h = c >> 6, d = c & 63;
                const size_t i0 = (((size_t)(b0i * Hh + h)) * Tt + t0) * 64 + d;
                const size_t i1 = (((size_t)(b1i * Hh + h)) * Tt + t1) * 64 + d;
                split_store(ohi, olo, i0, (acc[mt][nt][0] + bias[c]) * scale,
                                         (acc[mt][nt][1] + bias[c + 1]) * scale);
                split_store(ohi, olo, i1, (acc[mt][nt][2] + bias[c]) * scale,
                                         (acc[mt][nt][3] + bias[c + 1]) * scale);
            }
        }
    } else {
#pragma unroll
        for (int mt = 0; mt < 4; mt++) {
            const int r0 = m0 + wm * 64 + mt * 16 + g;
            const int r1 = r0 + 8;
#pragma unroll
            for (int nt = 0; nt < 4; nt++) {
                const int c = n_g + wn * 32 + nt * 8 + tq * 2;
                float2 v0 = {acc[mt][nt][0] + bias0[c], acc[mt][nt][1] + bias0[c + 1]};
                float2 v1 = {acc[mt][nt][2] + bias0[c], acc[mt][nt][3] + bias0[c + 1]};
                *(float2*)&outPlain[(size_t)r0 * Cc + c] = v0;
                *(float2*)&outPlain[(size_t)r1 * Cc + c] = v1;
            }
        }
    }
}

// ---------------- mma flash attention ----------------
// CTA: 128 q rows (blockIdx.x), one (b,h) (blockIdx.y). 8 warps x 16 q rows.
// kv chunks of 64; S and PV on mma.sync with 3-term bf16 splits.
__global__ __launch_bounds__(256) void attn_mma()
{
    extern __shared__ __align__(16) char smem_raw[];
    __nv_bfloat16* s = (__nv_bfloat16*)smem_raw;
    __nv_bfloat16 *sQhi = s, *sQlo = s + 9216;
    __nv_bfloat16 *sKhi = s + 18432, *sKlo = s + 23040;
    __nv_bfloat16 *sVhi = s + 27648, *sVlo = s + 32256;  // transposed [d][kv]

    const int bh = blockIdx.y, qb = blockIdx.x;
    const int tid = threadIdx.x, lane = tid & 31, wid = tid >> 5;
    const int g = lane >> 2, tq = lane & 3;

    const size_t hb = (size_t)bh * Tt * 64;

    // load Q tile (128 x 64) hi/lo
    {
        const int lrow = tid >> 1, lseg = (tid & 1) * 32;
        const __nv_bfloat16* ph = g_qhi + hb + (size_t)(qb * 128 + lrow) * 64 + lseg;
        const __nv_bfloat16* pl = g_qlo + hb + (size_t)(qb * 128 + lrow) * 64 + lseg;
#pragma unroll
        for (int i = 0; i < 4; i++) {
            *(uint4*)&sQhi[lrow * GP + lseg + i * 8] = *(const uint4*)(ph + i * 8);
            *(uint4*)&sQlo[lrow * GP + lseg + i * 8] = *(const uint4*)(pl + i * 8);
        }
    }
    __syncthreads();

    float m_i[2] = {-1e30f, -1e30f}, l_i[2] = {0.f, 0.f};
    float O[8][4];
#pragma unroll
    for (int nt = 0; nt < 8; nt++)
#pragma unroll
        for (int r = 0; r < 4; r++) O[nt][r] = 0.f;

    const int qrow0 = qb * 128 + wid * 16 + g;
    const int qrow1 = qrow0 + 8;
    const int nch = 2 * (qb + 1);

    for (int kb = 0; kb < nch; kb++) {
        // load K tile (64 x 64)
        {
            const int krow = tid >> 2, kseg = (tid & 3) * 16;
            const __nv_bfloat16* ph = g_khi + hb + (size_t)(kb * 64 + krow) * 64 + kseg;
            const __nv_bfloat16* pl = g_klo + hb + (size_t)(kb * 64 + krow) * 64 + kseg;
            *(uint4*)&sKhi[krow * GP + kseg]     = *(const uint4*)ph;
            *(uint4*)&sKhi[krow * GP + kseg + 8] = *(const uint4*)(ph + 8);
            *(uint4*)&sKlo[krow * GP + kseg]     = *(const uint4*)pl;
            *(uint4*)&sKlo[krow * GP + kseg + 8] = *(const uint4*)(pl + 8);
        }
        // load V tile transposed -> sV[d][kv]
        {
            const int vkv = tid & 63, vd0 = (tid >> 6) * 16;
            const __nv_bfloat16* ph = g_vhi + hb + (size_t)(kb * 64 + vkv) * 64 + vd0;
            const __nv_bfloat16* pl = g_vlo + hb + (size_t)(kb * 64 + vkv) * 64 + vd0;
            uint4 h0 = *(const uint4*)ph, h1 = *(const uint4*)(ph + 8);
            uint4 l0 = *(const uint4*)pl, l1 = *(const uint4*)(pl + 8);
            const __nv_bfloat16* eh0 = (const __nv_bfloat16*)&h0;
            const __nv_bfloat16* eh1 = (const __nv_bfloat16*)&h1;
            const __nv_bfloat16* el0 = (const __nv_bfloat16*)&l0;
            const __nv_bfloat16* el1 = (const __nv_bfloat16*)&l1;
#pragma unroll
            for (int j = 0; j < 8; j++) {
                sVhi[(vd0 + j) * GP + vkv]     = eh0[j];
                sVhi[(vd0 + 8 + j) * GP + vkv] = eh1[j];
                sVlo[(vd0 + j) * GP + vkv]     = el0[j];
                sVlo[(vd0 + 8 + j) * GP + vkv] = el1[j];
            }
        }
        __syncthreads();

        const bool active = (kb * 64) <= (qb * 128 + wid * 16 + 15);
        if (active) {
            float S[8][4];
#pragma unroll
            for (int nt = 0; nt < 8; nt++)
#pragma unroll
                for (int r = 0; r < 4; r++) S[nt][r] = 0.f;

            // S = Q K^T
#pragma unroll
            for (int ks = 0; ks < 4; ks++) {
                const int tk = ks * 16 + tq * 2;
                const int r = wid * 16 + g;
                uint32_t ahi[4], alo[4];
                ahi[0] = *(const uint32_t*)&sQhi[r * GP + tk];
                ahi[1] = *(const uint32_t*)&sQhi[(r + 8) * GP + tk];
                ahi[2] = *(const uint32_t*)&sQhi[r * GP + tk + 8];
                ahi[3] = *(const uint32_t*)&sQhi[(r + 8) * GP + tk + 8];
                alo[0] = *(const uint32_t*)&sQlo[r * GP + tk];
                alo[1] = *(const uint32_t*)&sQlo[(r + 8) * GP + tk];
                alo[2] = *(const uint32_t*)&sQlo[r * GP + tk + 8];
                alo[3] = *(const uint32_t*)&sQlo[(r + 8) * GP + tk + 8];
#pragma unroll
                for (int nt = 0; nt < 8; nt++) {
                    const int cb = nt * 8 + g;
                    uint32_t bhi[2] = {*(const uint32_t*)&sKhi[cb * GP + tk],
                                       *(const uint32_t*)&sKhi[cb * GP + tk + 8]};
                    uint32_t blo[2] = {*(const uint32_t*)&sKlo[cb * GP + tk],
                                       *(const uint32_t*)&sKlo[cb * GP + tk + 8]};
                    mma_bf16(S[nt], ahi, bhi);
                    mma_bf16(S[nt], ahi, blo);
                    mma_bf16(S[nt], alo, bhi);
                }
            }

            // causal mask
            if (kb * 64 + 63 > qrow0) {
#pragma unroll
                for (int nt = 0; nt < 8; nt++) {
#pragma unroll
                    for (int j = 0; j < 2; j++) {
                        const int col = kb * 64 + nt * 8 + tq * 2 + j;
                        if (col > qrow0) S[nt][j]     = -1e30f;
                        if (col > qrow1) S[nt][2 + j] = -1e30f;
                    }
                }
            }

            // online softmax (rows live in 4-lane groups)
            float mx0 = -1e30f, mx1 = -1e30f;
#pragma unroll
            for (int nt = 0; nt < 8; nt++) {
                mx0 = fmaxf(mx0, fmaxf(S[nt][0], S[nt][1]));
                mx1 = fmaxf(mx1, fmaxf(S[nt][2], S[nt][3]));
            }
            mx0 = fmaxf(mx0, __shfl_xor_sync(0xffffffffu, mx0, 1));
            mx0 = fmaxf(mx0, __shfl_xor_sync(0xffffffffu, mx0, 2));
            mx1 = fmaxf(mx1, __shfl_xor_sync(0xffffffffu, mx1, 1));
            mx1 = fmaxf(mx1, __shfl_xor_sync(0xffffffffu, mx1, 2));

            const float mn0 = fmaxf(m_i[0], mx0), mn1 = fmaxf(m_i[1], mx1);
            const float cr0 = __expf(m_i[0] - mn0), cr1 = __expf(m_i[1] - mn1);
            m_i[0] = mn0; m_i[1] = mn1;

            float s0 = 0.f, s1 = 0.f;
#pragma unroll
            for (int nt = 0; nt < 8; nt++) {
                S[nt][0] = __expf(S[nt][0] - mn0);
                S[nt][1] = __expf(S[nt][1] - mn0);
                S[nt][2] = __expf(S[nt][2] - mn1);
                S[nt][3] = __expf(S[nt][3] - mn1);
                s0 += S[nt][0] + S[nt][1];
                s1 += S[nt][2] + S[nt][3];
            }
            s0 += __shfl_xor_sync(0xffffffffu, s0, 1);
            s0 += __shfl_xor_sync(0xffffffffu, s0, 2);
            s1 += __shfl_xor_sync(0xffffffffu, s1, 1);
            s1 += __shfl_xor_sync(0xffffffffu, s1, 2);
            l_i[0] = l_i[0] * cr0 + s0;
            l_i[1] = l_i[1] * cr1 + s1;
#pragma unroll
            for (int nt = 0; nt < 8; nt++) {
                O[nt][0] *= cr0; O[nt][1] *= cr0;
                O[nt][2] *= cr1; O[nt][3] *= cr1;
            }

            // O += P V   (P built in-register from S)
#pragma unroll
            for (int ks = 0; ks < 4; ks++) {
                const int n0t = 2 * ks, n1t = 2 * ks + 1;
                uint32_t phi[4], plo[4];
                phi[0] = pack2(S[n0t][0], S[n0t][1]);
                phi[1] = pack2(S[n0t][2], S[n0t][3]);
                phi[2] = pack2(S[n1t][0], S[n1t][1]);
                phi[3] = pack2(S[n1t][2], S[n1t][3]);
                plo[0] = pack2(bres(S[n0t][0]), bres(S[n0t][1]));
                plo[1] = pack2(bres(S[n0t][2]), bres(S[n0t][3]));
                plo[2] = pack2(bres(S[n1t][0]), bres(S[n1t][1]));
                plo[3] = pack2(bres(S[n1t][2]), bres(S[n1t][3]));
                const int tk = ks * 16 + tq * 2;
#pragma unroll
                for (int nt = 0; nt < 8; nt++) {
                    const int cb = nt * 8 + g;
                    uint32_t bhi[2] = {*(const uint32_t*)&sVhi[cb * GP + tk],
                                       *(const uint32_t*)&sVhi[cb * GP + tk + 8]};
                    uint32_t blo[2] = {*(const uint32_t*)&sVlo[cb * GP + tk],
                                       *(const uint32_t*)&sVlo[cb * GP + tk + 8]};
                    mma_bf16(O[nt], phi, bhi);
                    mma_bf16(O[nt], phi, blo);
                    mma_bf16(O[nt], plo, bhi);
                }
            }
        }
        __syncthreads();
    }

    // epilogue: ctx split store
    const float inv0 = 1.f / l_i[0], inv1 = 1.f / l_i[1];
    const int b = bh >> 4, h = bh & 15;
    const size_t row0 = ((size_t)b * Tt + qrow0 - 0) * Cc;   // qrow0 is global t already? no:
    // qrow0 = qb*128 + wid*16 + g is the t index within this (b,h); ctx row = b*T + t
    const size_t r0 = ((size_t)b * Tt + (qb * 128 + wid * 16 + g)) * Cc;
    const size_t r1 = r0 + 8 * Cc;
    (void)row0;
#pragma unroll
    for (int nt = 0; nt < 8; nt++) {
        const int c = h * 64 + nt * 8 + tq * 2;
        split_store(g_chi, g_clo, r0 + c, O[nt][0] * inv0, O[nt][1] * inv0);
        split_store(g_chi, g_clo, r1 + c, O[nt][2] * inv1, O[nt][3] * inv1);
    }
}

// ---------------- launch ----------------
extern "C" void kernel_launch(void* const* d_in, const int* in_sizes, int n_in,
                              void* d_out, int out_size)
{
    (void)in_sizes; (void)n_in; (void)out_size;
    const float* hs = (const float*)d_in[0];
    const float* Wq = (const float*)d_in[2];
    const float* bq = (const float*)d_in[3];
    const float* Wk = (const float*)d_in[4];
    const float* bk = (const float*)d_in[5];
    const float* Wv = (const float*)d_in[6];
    const float* bv = (const float*)d_in[7];
    const float* Wo = (const float*)d_in[8];
    const float* bo = (const float*)d_in[9];

    cudaFuncSetAttribute(mma_gemm, cudaFuncAttributeMaxDynamicSharedMemorySize, 73728);
    cudaFuncSetAttribute(attn_mma, cudaFuncAttributeMaxDynamicSharedMemorySize, 73728);

    split_hs<<<4096, 256>>>(hs);
    wsplit<<<dim3(32, 32), 256>>>(Wq, 0);
    wsplit<<<dim3(32, 32), 256>>>(Wk, 1);
    wsplit<<<dim3(32, 32), 256>>>(Wv, 2);
    wsplit<<<dim3(32, 32), 256>>>(Wo, 3);

    mma_gemm<<<dim3(24, 32), 256, 73728>>>(bq, bk, bv, nullptr, 0);
    attn_mma<<<dim3(16, 32), 256, 73728>>>();
    mma_gemm<<<dim3(8, 32), 256, 73728>>>(bo, nullptr, nullptr, (float*)d_out, 1);
}

// round 4
// speedup vs baseline: 2.7905x; 1.1591x over previous
#include <cuda_runtime.h>
#include <cuda_bf16.h>
#include <cstdint>

#define Tt 2048
#define Cc 1024
#define Hh 16
#define Mm 4096
#define MB1 (1024*1024)

// ---------------- static device scratch ----------------
__device__ __nv_bfloat16 g_ahi[Mm*Cc], g_alo[Mm*Cc];     // hidden_states split
__device__ __nv_bfloat16 g_qhi[Mm*Cc], g_qlo[Mm*Cc];     // [B*H, T, 64], pre-scaled
__device__ __nv_bfloat16 g_khi[Mm*Cc], g_klo[Mm*Cc];
__device__ __nv_bfloat16 g_vhi[Mm*Cc], g_vlo[Mm*Cc];
__device__ __nv_bfloat16 g_chi[Mm*Cc], g_clo[Mm*Cc];     // ctx split [M, C]
__device__ __nv_bfloat16 g_wt_hi[3*MB1], g_wt_lo[3*MB1]; // Wq^T|Wk^T|Wv^T [N,K]
__device__ __nv_bfloat16 g_wo_hi[MB1],  g_wo_lo[MB1];    // Wo^T [N,K]

// ---------------- helpers ----------------
__device__ __forceinline__ uint32_t smem_u32(const void* p) {
    uint32_t a;
    asm("{ .reg .u64 t; cvta.to.shared.u64 t, %1; cvt.u32.u64 %0, t; }" : "=r"(a) : "l"(p));
    return a;
}
__device__ __forceinline__ void mma_bf16(float c[4], const uint32_t a[4], const uint32_t b[2]) {
    asm volatile(
        "mma.sync.aligned.m16n8k16.row.col.f32.bf16.bf16.f32 "
        "{%0,%1,%2,%3}, {%4,%5,%6,%7}, {%8,%9}, {%0,%1,%2,%3};"
        : "+f"(c[0]), "+f"(c[1]), "+f"(c[2]), "+f"(c[3])
        : "r"(a[0]), "r"(a[1]), "r"(a[2]), "r"(a[3]), "r"(b[0]), "r"(b[1]));
}
__device__ __forceinline__ void ldm4(uint32_t* r, uint32_t a) {
    asm volatile("ldmatrix.sync.aligned.m8n8.x4.shared.b16 {%0,%1,%2,%3}, [%4];"
        : "=r"(r[0]), "=r"(r[1]), "=r"(r[2]), "=r"(r[3]) : "r"(a));
}
__device__ __forceinline__ void ldm4t(uint32_t* r, uint32_t a) {
    asm volatile("ldmatrix.sync.aligned.m8n8.x4.trans.shared.b16 {%0,%1,%2,%3}, [%4];"
        : "=r"(r[0]), "=r"(r[1]), "=r"(r[2]), "=r"(r[3]) : "r"(a));
}
__device__ __forceinline__ void cp16(uint32_t d, const void* s) {
    asm volatile("cp.async.cg.shared.global [%0], [%1], 16;" :: "r"(d), "l"(s));
}
#define CP_COMMIT() asm volatile("cp.async.commit_group;" ::: "memory")
#define CP_WAIT(n)  asm volatile("cp.async.wait_group %0;" :: "n"(n) : "memory")

__device__ __forceinline__ uint32_t pack2(float x, float y) {
    __nv_bfloat162 t;
    t.x = __float2bfloat16(x);
    t.y = __float2bfloat16(y);
    return *(uint32_t*)&t;
}
__device__ __forceinline__ float bres(float x) {
    return x - __bfloat162float(__float2bfloat16(x));
}
__device__ __forceinline__ void split_store(__nv_bfloat16* hi, __nv_bfloat16* lo,
                                            size_t idx, float a, float b) {
    __nv_bfloat16 ha = __float2bfloat16(a), hb = __float2bfloat16(b);
    __nv_bfloat162 hv; hv.x = ha; hv.y = hb;
    *(__nv_bfloat162*)&hi[idx] = hv;
    __nv_bfloat162 lv;
    lv.x = __float2bfloat16(a - __bfloat162float(ha));
    lv.y = __float2bfloat16(b - __bfloat162float(hb));
    *(__nv_bfloat162*)&lo[idx] = lv;
}

// ---------------- split kernels ----------------
__global__ __launch_bounds__(256) void split_hs(const float* __restrict__ src)
{
    size_t i0 = ((size_t)blockIdx.x * 256 + threadIdx.x) * 4;
    float4 x = *(const float4*)(src + i0);
    float xs[4] = {x.x, x.y, x.z, x.w};
#pragma unroll
    for (int j = 0; j < 4; j++) {
        __nv_bfloat16 h = __float2bfloat16(xs[j]);
        g_ahi[i0 + j] = h;
        g_alo[i0 + j] = __float2bfloat16(xs[j] - __bfloat162float(h));
    }
}

__global__ __launch_bounds__(256) void wsplit(const float* __restrict__ W, int widx)
{
    __shared__ float tile[32][33];
    __nv_bfloat16* hi = (widx < 3) ? (g_wt_hi + (size_t)widx * MB1) : g_wo_hi;
    __nv_bfloat16* lo = (widx < 3) ? (g_wt_lo + (size_t)widx * MB1) : g_wo_lo;
    const int tx = threadIdx.x & 31, ty0 = threadIdx.x >> 5;
    const int n0 = blockIdx.x * 32, k0 = blockIdx.y * 32;
#pragma unroll
    for (int r = ty0; r < 32; r += 8)
        tile[r][tx] = W[(size_t)(k0 + r) * Cc + n0 + tx];
    __syncthreads();
#pragma unroll
    for (int r = ty0; r < 32; r += 8) {
        float xv = tile[tx][r];
        __nv_bfloat16 h = __float2bfloat16(xv);
        hi[(size_t)(n0 + r) * Cc + k0 + tx] = h;
        lo[(size_t)(n0 + r) * Cc + k0 + tx] = __float2bfloat16(xv - __bfloat162float(h));
    }
}

// ---------------- pipelined split-bf16 mma GEMM ----------------
// 128x128 CTA tile, K-chunk 32, 3-stage cp.async, ldmatrix fragments.
#define G_MAT 10240              // 128 rows * 80B
#define G_STG 40960              // Ahi|Alo|Bhi|Blo
#define G_SMEM (3*G_STG)         // 122880

__global__ __launch_bounds__(256) void mma_gemm(
    const float* __restrict__ bias0, const float* __restrict__ bias1,
    const float* __restrict__ bias2, float* __restrict__ outPlain, int mode)
{
    extern __shared__ __align__(16) char smem_raw[];
    const uint32_t sb = smem_u32(smem_raw);

    const int tid = threadIdx.x, lane = tid & 31, wid = tid >> 5;
    const int wm = wid >> 2, wn = wid & 3;
    const int g = lane >> 2, tq = lane & 3;
    const int m0 = blockIdx.y * 128, n_g = blockIdx.x * 128;

    const __nv_bfloat16* Ahi = (mode == 0) ? g_ahi : g_chi;
    const __nv_bfloat16* Alo = (mode == 0) ? g_alo : g_clo;
    const __nv_bfloat16* Bhi = (mode == 0) ? g_wt_hi : g_wo_hi;
    const __nv_bfloat16* Blo = (mode == 0) ? g_wt_lo : g_wo_lo;

    const int lr = tid >> 1;
    const int ls = (tid & 1) * 2;
    const size_t ga_row = (size_t)(m0 + lr) * Cc;
    const size_t gb_row = (size_t)(n_g + lr) * Cc;

    auto load_chunk = [&](int ch, int st) {
        const uint32_t base = sb + st * G_STG + lr * 80 + ls * 16;
        const int gc = ch * 32 + ls * 8;
#pragma unroll
        for (int j = 0; j < 2; j++) {
            cp16(base + 0 * G_MAT + j * 16, Ahi + ga_row + gc + j * 8);
            cp16(base + 1 * G_MAT + j * 16, Alo + ga_row + gc + j * 8);
            cp16(base + 2 * G_MAT + j * 16, Bhi + gb_row + gc + j * 8);
            cp16(base + 3 * G_MAT + j * 16, Blo + gb_row + gc + j * 8);
        }
    };

    float acc[4][4][4];
#pragma unroll
    for (int i = 0; i < 4; i++)
#pragma unroll
        for (int j = 0; j < 4; j++)
#pragma unroll
            for (int r = 0; r < 4; r++) acc[i][j][r] = 0.f;

    load_chunk(0, 0); CP_COMMIT();
    load_chunk(1, 1); CP_COMMIT();

    const int arow = lane & 15;
    const int acol = (lane >> 4) * 16;                 // byte offset (+8 elems)
    const int brow = (lane & 7) + ((lane >> 4) & 1) * 8;
    const int bcol = ((lane >> 3) & 1) * 16;

    for (int ch = 0; ch < 32; ch++) {
        CP_WAIT(1);
        __syncthreads();
        if (ch + 2 < 32) load_chunk(ch + 2, (ch + 2) % 3);
        CP_COMMIT();

        const uint32_t st = sb + (ch % 3) * G_STG;
#pragma unroll
        for (int ks = 0; ks < 2; ks++) {
            const int kb = ks * 32;                    // k0 byte offset
            uint32_t ahi[4][4], alo[4][4];
#pragma unroll
            for (int mt = 0; mt < 4; mt++) {
                const uint32_t ra = st + (uint32_t)(wm * 64 + mt * 16 + arow) * 80 + kb + acol;
                ldm4(ahi[mt], ra);
                ldm4(alo[mt], ra + G_MAT);
            }
#pragma unroll
            for (int p = 0; p < 2; p++) {
                const uint32_t rb = st + 2 * G_MAT +
                    (uint32_t)(wn * 32 + p * 16 + brow) * 80 + kb + bcol;
                uint32_t bh4[4], bl4[4];
                ldm4(bh4, rb);
                ldm4(bl4, rb + G_MAT);
#pragma unroll
                for (int e = 0; e < 2; e++) {
                    const int nt = p * 2 + e;
                    const uint32_t bh2[2] = {bh4[e * 2], bh4[e * 2 + 1]};
                    const uint32_t bl2[2] = {bl4[e * 2], bl4[e * 2 + 1]};
#pragma unroll
                    for (int mt = 0; mt < 4; mt++) {
                        mma_bf16(acc[mt][nt], ahi[mt], bh2);
                        mma_bf16(acc[mt][nt], ahi[mt], bl2);
                        mma_bf16(acc[mt][nt], alo[mt], bh2);
                    }
                }
            }
        }
    }

    if (mode == 0) {
        const int which = n_g >> 10;
        const int nloc = n_g & 1023;
        const float* bias = (which == 0) ? bias0 : (which == 1) ? bias1 : bias2;
        __nv_bfloat16* ohi = (which == 0) ? g_qhi : (which == 1) ? g_khi : g_vhi;
        __nv_bfloat16* olo = (which == 0) ? g_qlo : (which == 1) ? g_klo : g_vlo;
        const float scale = (which == 0) ? 0.125f : 1.0f;
#pragma unroll
        for (int mt = 0; mt < 4; mt++) {
            const int r0 = m0 + wm * 64 + mt * 16 + g;
            const int r1 = r0 + 8;
            const int b0i = r0 >> 11, t0 = r0 & 2047;
            const int b1i = r1 >> 11, t1 = r1 & 2047;
#pragma unroll
            for (int nt = 0; nt < 4; nt++) {
                const int c = nloc + wn * 32 + nt * 8 + tq * 2;
                const int h = c >> 6, d = c & 63;
                const size_t i0 = (((size_t)(b0i * Hh + h)) * Tt + t0) * 64 + d;
                const size_t i1 = (((size_t)(b1i * Hh + h)) * Tt + t1) * 64 + d;
                split_store(ohi, olo, i0, (acc[mt][nt][0] + bias[c]) * scale,
                                         (acc[mt][nt][1] + bias[c + 1]) * scale);
                split_store(ohi, olo, i1, (acc[mt][nt][2] + bias[c]) * scale,
                                         (acc[mt][nt][3] + bias[c + 1]) * scale);
            }
        }
    } else {
#pragma unroll
        for (int mt = 0; mt < 4; mt++) {
            const int r0 = m0 + wm * 64 + mt * 16 + g;
            const int r1 = r0 + 8;
#pragma unroll
            for (int nt = 0; nt < 4; nt++) {
                const int c = n_g + wn * 32 + nt * 8 + tq * 2;
                float2 v0 = {acc[mt][nt][0] + bias0[c], acc[mt][nt][1] + bias0[c + 1]};
                float2 v1 = {acc[mt][nt][2] + bias0[c], acc[mt][nt][3] + bias0[c + 1]};
                *(float2*)&outPlain[(size_t)r0 * Cc + c] = v0;
                *(float2*)&outPlain[(size_t)r1 * Cc + c] = v1;
            }
        }
    }
}

// ---------------- pipelined mma flash attention ----------------
// 128 q rows / CTA, K/V chunks of 64 double-buffered via cp.async,
// Q fragments register-resident, ldmatrix (+trans for V).
#define A_MAT 9216               // 64 rows * 144B
#define A_STG 36864              // Khi|Klo|Vhi|Vlo
#define A_SMEM 73728

__global__ __launch_bounds__(256) void attn_mma()
{
    extern __shared__ __align__(16) char smem_raw[];
    const uint32_t sb = smem_u32(smem_raw);

    const int bh = blockIdx.y;
    const int qb = (int)gridDim.x - 1 - (int)blockIdx.x;   // heavy tiles first
    const int tid = threadIdx.x, lane = tid & 31, wid = tid >> 5;
    const int g = lane >> 2, tq = lane & 3;

    const size_t hb = (size_t)bh * Tt * 64;
    const int nch = 2 * (qb + 1);

    const int lr = tid >> 2;              // 0..63
    const int ls = (tid & 3) * 2;         // 16B-seg base

    auto load_kv = [&](int kb, int st) {
        const uint32_t base = sb + st * A_STG + lr * 144 + ls * 16;
        const size_t gr = hb + (size_t)(kb * 64 + lr) * 64 + ls * 8;
#pragma unroll
        for (int j = 0; j < 2; j++) {
            cp16(base + 0 * A_MAT + j * 16, g_khi + gr + j * 8);
            cp16(base + 1 * A_MAT + j * 16, g_klo + gr + j * 8);
            cp16(base + 2 * A_MAT + j * 16, g_vhi + gr + j * 8);
            cp16(base + 3 * A_MAT + j * 16, g_vlo + gr + j * 8);
        }
    };

    load_kv(0, 0); CP_COMMIT();

    // stage Q (hi/lo) into stage-1 region, then lift fragments to registers
    {
        const int qr = tid >> 1;
        const int qs = (tid & 1) * 32;
        const __nv_bfloat16* ph = g_qhi + hb + (size_t)(qb * 128 + qr) * 64 + qs;
        const __nv_bfloat16* pl = g_qlo + hb + (size_t)(qb * 128 + qr) * 64 + qs;
        char* dh = smem_raw + A_STG + qr * 144 + qs * 2;
        char* dl = smem_raw + A_STG + 18432 + qr * 144 + qs * 2;
#pragma unroll
        for (int i = 0; i < 4; i++) {
            *(uint4*)(dh + i * 16) = *(const uint4*)(ph + i * 8);
            *(uint4*)(dl + i * 16) = *(const uint4*)(pl + i * 8);
        }
    }
    __syncthreads();

    const int arow = lane & 15;
    const int acol = (lane >> 4) * 16;
    uint32_t qfh[4][4], qfl[4][4];
#pragma unroll
    for (int ks = 0; ks < 4; ks++) {
        const uint32_t qa = sb + A_STG + (uint32_t)(wid * 16 + arow) * 144 + ks * 32 + acol;
        ldm4(qfh[ks], qa);
        ldm4(qfl[ks], qa + 18432);
    }
    __syncthreads();   // Q frags captured before stage-1 is overwritten

    float m_i[2] = {-1e30f, -1e30f}, l_i[2] = {0.f, 0.f};
    float O[8][4];
#pragma unroll
    for (int nt = 0; nt < 8; nt++)
#pragma unroll
        for (int r = 0; r < 4; r++) O[nt][r] = 0.f;

    const int qrow0 = qb * 128 + wid * 16 + g;
    const int qrow1 = qrow0 + 8;

    const int brow = (lane & 7) + ((lane >> 4) & 1) * 8;
    const int bcol = ((lane >> 3) & 1) * 16;
    const int vrow = (lane & 7) + ((lane >> 3) & 1) * 8;
    const int vcol = ((lane >> 4) & 1) * 16;

    for (int kb = 0; kb < nch; kb++) {
        CP_WAIT(0);
        __syncthreads();
        if (kb + 1 < nch) load_kv(kb + 1, (kb + 1) & 1);
        CP_COMMIT();

        const uint32_t st = sb + (kb & 1) * A_STG;
        const bool active = (kb * 64) <= (qb * 128 + wid * 16 + 15);
        if (active) {
            float S[8][4];
#pragma unroll
            for (int nt = 0; nt < 8; nt++)
#pragma unroll
                for (int r = 0; r < 4; r++) S[nt][r] = 0.f;

            // S = Q K^T
#pragma unroll
            for (int ks = 0; ks < 4; ks++) {
#pragma unroll
                for (int p = 0; p < 4; p++) {
                    const uint32_t rb = st + (uint32_t)(p * 16 + brow) * 144 + ks * 32 + bcol;
                    uint32_t kh4[4], kl4[4];
                    ldm4(kh4, rb);
                    ldm4(kl4, rb + A_MAT);
#pragma unroll
                    for (int e = 0; e < 2; e++) {
                        const int nt = p * 2 + e;
                        const uint32_t bh2[2] = {kh4[e * 2], kh4[e * 2 + 1]};
                        const uint32_t bl2[2] = {kl4[e * 2], kl4[e * 2 + 1]};
                        mma_bf16(S[nt], qfh[ks], bh2);
                        mma_bf16(S[nt], qfh[ks], bl2);
                        mma_bf16(S[nt], qfl[ks], bh2);
                    }
                }
            }

            // causal mask
            if (kb * 64 + 63 > qrow0) {
#pragma unroll
                for (int nt = 0; nt < 8; nt++) {
#pragma unroll
                    for (int j = 0; j < 2; j++) {
                        const int col = kb * 64 + nt * 8 + tq * 2 + j;
                        if (col > qrow0) S[nt][j]     = -1e30f;
                        if (col > qrow1) S[nt][2 + j] = -1e30f;
                    }
                }
            }

            // online softmax
            float mx0 = -1e30f, mx1 = -1e30f;
#pragma unroll
            for (int nt = 0; nt < 8; nt++) {
                mx0 = fmaxf(mx0, fmaxf(S[nt][0], S[nt][1]));
                mx1 = fmaxf(mx1, fmaxf(S[nt][2], S[nt][3]));
            }
            mx0 = fmaxf(mx0, __shfl_xor_sync(0xffffffffu, mx0, 1));
            mx0 = fmaxf(mx0, __shfl_xor_sync(0xffffffffu, mx0, 2));
            mx1 = fmaxf(mx1, __shfl_xor_sync(0xffffffffu, mx1, 1));
            mx1 = fmaxf(mx1, __shfl_xor_sync(0xffffffffu, mx1, 2));

            const float mn0 = fmaxf(m_i[0], mx0), mn1 = fmaxf(m_i[1], mx1);
            const float cr0 = __expf(m_i[0] - mn0), cr1 = __expf(m_i[1] - mn1);
            m_i[0] = mn0; m_i[1] = mn1;

            float s0 = 0.f, s1 = 0.f;
#pragma unroll
            for (int nt = 0; nt < 8; nt++) {
                S[nt][0] = __expf(S[nt][0] - mn0);
                S[nt][1] = __expf(S[nt][1] - mn0);
                S[nt][2] = __expf(S[nt][2] - mn1);
                S[nt][3] = __expf(S[nt][3] - mn1);
                s0 += S[nt][0] + S[nt][1];
                s1 += S[nt][2] + S[nt][3];
            }
            s0 += __shfl_xor_sync(0xffffffffu, s0, 1);
            s0 += __shfl_xor_sync(0xffffffffu, s0, 2);
            s1 += __shfl_xor_sync(0xffffffffu, s1, 1);
            s1 += __shfl_xor_sync(0xffffffffu, s1, 2);
            l_i[0] = l_i[0] * cr0 + s0;
            l_i[1] = l_i[1] * cr1 + s1;
#pragma unroll
            for (int nt = 0; nt < 8; nt++) {
                O[nt][0] *= cr0; O[nt][1] *= cr0;
                O[nt][2] *= cr1; O[nt][3] *= cr1;
            }

            // O += P V  (V fragments via ldmatrix.trans)
#pragma unroll
            for (int ks = 0; ks < 4; ks++) {
                const int n0t = 2 * ks, n1t = 2 * ks + 1;
                uint32_t phi[4], plo[4];
                phi[0] = pack2(S[n0t][0], S[n0t][1]);
                phi[1] = pack2(S[n0t][2], S[n0t][3]);
                phi[2] = pack2(S[n1t][0], S[n1t][1]);
                phi[3] = pack2(S[n1t][2], S[n1t][3]);
                plo[0] = pack2(bres(S[n0t][0]), bres(S[n0t][1]));
                plo[1] = pack2(bres(S[n0t][2]), bres(S[n0t][3]));
                plo[2] = pack2(bres(S[n1t][0]), bres(S[n1t][1]));
                plo[3] = pack2(bres(S[n1t][2]), bres(S[n1t][3]));
#pragma unroll
                for (int p = 0; p < 4; p++) {
                    const uint32_t rv = st + 2 * A_MAT +
                        (uint32_t)(ks * 16 + vrow) * 144 + p * 32 + vcol;
                    uint32_t vh4[4], vl4[4];
                    ldm4t(vh4, rv);
                    ldm4t(vl4, rv + A_MAT);
#pragma unroll
                    for (int e = 0; e < 2; e++) {
                        const int nt = p * 2 + e;
                        const uint32_t bh2[2] = {vh4[e * 2], vh4[e * 2 + 1]};
                        const uint32_t bl2[2] = {vl4[e * 2], vl4[e * 2 + 1]};
                        mma_bf16(O[nt], phi, bh2);
                        mma_bf16(O[nt], phi, bl2);
                        mma_bf16(O[nt], plo, bh2);
                    }
                }
            }
        }
    }

    // epilogue: split ctx store
    const float inv0 = 1.f / l_i[0], inv1 = 1.f / l_i[1];
    const int b = bh >> 4, h = bh & 15;
    const size_t r0 = ((size_t)b * Tt + (qb * 128 + wid * 16 + g)) * Cc;
    const size_t r1 = r0 + 8 * Cc;
#pragma unroll
    for (int nt = 0; nt < 8; nt++) {
        const int c = h * 64 + nt * 8 + tq * 2;
        split_store(g_chi, g_clo, r0 + c, O[nt][0] * inv0, O[nt][1] * inv0);
        split_store(g_chi, g_clo, r1 + c, O[nt][2] * inv1, O[nt][3] * inv1);
    }
}

// ---------------- launch ----------------
extern "C" void kernel_launch(void* const* d_in, const int* in_sizes, int n_in,
                              void* d_out, int out_size)
{
    (void)in_sizes; (void)n_in; (void)out_size;
    const float* hs = (const float*)d_in[0];
    const float* Wq = (const float*)d_in[2];
    const float* bq = (const float*)d_in[3];
    const float* Wk = (const float*)d_in[4];
    const float* bk = (const float*)d_in[5];
    const float* Wv = (const float*)d_in[6];
    const float* bv = (const float*)d_in[7];
    const float* Wo = (const float*)d_in[8];
    const float* bo = (const float*)d_in[9];

    cudaFuncSetAttribute(mma_gemm, cudaFuncAttributeMaxDynamicSharedMemorySize, G_SMEM);
    cudaFuncSetAttribute(attn_mma, cudaFuncAttributeMaxDynamicSharedMemorySize, A_SMEM);

    split_hs<<<4096, 256>>>(hs);
    wsplit<<<dim3(32, 32), 256>>>(Wq, 0);
    wsplit<<<dim3(32, 32), 256>>>(Wk, 1);
    wsplit<<<dim3(32, 32), 256>>>(Wv, 2);
    wsplit<<<dim3(32, 32), 256>>>(Wo, 3);

    mma_gemm<<<dim3(24, 32), 256, G_SMEM>>>(bq, bk, bv, nullptr, 0);
    attn_mma<<<dim3(16, 32), 256, A_SMEM>>>();
    mma_gemm<<<dim3(8, 32), 256, G_SMEM>>>(bo, nullptr, nullptr, (float*)d_out, 1);
}

// round 5
// speedup vs baseline: 4.0123x; 1.4378x over previous
#include <cuda_runtime.h>
#include <cuda_fp16.h>
#include <cstdint>

#define Tt 2048
#define Cc 1024
#define Hh 16
#define Mm 4096
#define MB1 (1024*1024)

// ---------------- static device scratch ----------------
__device__ __half g_ahi[Mm*Cc], g_alo[Mm*Cc];   // hidden_states split (fp16 hi/lo)
__device__ __half g_qhi[Mm*Cc], g_qlo[Mm*Cc];   // Q [B*H,T,64] split, pre-scaled
__device__ __half g_k[Mm*Cc];                   // K single fp16
__device__ __half g_v[Mm*Cc];                   // V single fp16
__device__ __half g_chi[Mm*Cc], g_clo[Mm*Cc];   // ctx split [M,C]
__device__ __half g_w[4*MB1];                   // Wq^T|Wk^T|Wv^T|Wo^T [N,K] fp16

// ---------------- helpers ----------------
__device__ __forceinline__ uint32_t smem_u32(const void* p) {
    uint32_t a;
    asm("{ .reg .u64 t; cvta.to.shared.u64 t, %1; cvt.u32.u64 %0, t; }" : "=r"(a) : "l"(p));
    return a;
}
__device__ __forceinline__ void mma_f16(float c[4], const uint32_t a[4], const uint32_t b[2]) {
    asm volatile(
        "mma.sync.aligned.m16n8k16.row.col.f32.f16.f16.f32 "
        "{%0,%1,%2,%3}, {%4,%5,%6,%7}, {%8,%9}, {%0,%1,%2,%3};"
        : "+f"(c[0]), "+f"(c[1]), "+f"(c[2]), "+f"(c[3])
        : "r"(a[0]), "r"(a[1]), "r"(a[2]), "r"(a[3]), "r"(b[0]), "r"(b[1]));
}
__device__ __forceinline__ void ldm4(uint32_t* r, uint32_t a) {
    asm volatile("ldmatrix.sync.aligned.m8n8.x4.shared.b16 {%0,%1,%2,%3}, [%4];"
        : "=r"(r[0]), "=r"(r[1]), "=r"(r[2]), "=r"(r[3]) : "r"(a));
}
__device__ __forceinline__ void ldm4t(uint32_t* r, uint32_t a) {
    asm volatile("ldmatrix.sync.aligned.m8n8.x4.trans.shared.b16 {%0,%1,%2,%3}, [%4];"
        : "=r"(r[0]), "=r"(r[1]), "=r"(r[2]), "=r"(r[3]) : "r"(a));
}
__device__ __forceinline__ void cp16(uint32_t d, const void* s) {
    asm volatile("cp.async.cg.shared.global [%0], [%1], 16;" :: "r"(d), "l"(s));
}
#define CP_COMMIT() asm volatile("cp.async.commit_group;" ::: "memory")
#define CP_WAIT(n)  asm volatile("cp.async.wait_group %0;" :: "n"(n) : "memory")

__device__ __forceinline__ uint32_t pack2h(float x, float y) {
    __half2 t;
    t.x = __float2half_rn(x);
    t.y = __float2half_rn(y);
    return *(uint32_t*)&t;
}
__device__ __forceinline__ float hres(float x) {
    return x - __half2float(__float2half_rn(x));
}
__device__ __forceinline__ void split_store_h(__half* hi, __half* lo,
                                              size_t idx, float a, float b) {
    __half ha = __float2half_rn(a), hb = __float2half_rn(b);
    __half2 hv; hv.x = ha; hv.y = hb;
    *(__half2*)&hi[idx] = hv;
    __half2 lv;
    lv.x = __float2half_rn(a - __half2float(ha));
    lv.y = __float2half_rn(b - __half2float(hb));
    *(__half2*)&lo[idx] = lv;
}

// ---------------- prep kernels ----------------
__global__ __launch_bounds__(256) void split_hs(const float* __restrict__ src)
{
    size_t i0 = ((size_t)blockIdx.x * 256 + threadIdx.x) * 4;
    float4 x = *(const float4*)(src + i0);
    float xs[4] = {x.x, x.y, x.z, x.w};
#pragma unroll
    for (int j = 0; j < 4; j++) {
        __half h = __float2half_rn(xs[j]);
        g_ahi[i0 + j] = h;
        g_alo[i0 + j] = __float2half_rn(xs[j] - __half2float(h));
    }
}

__global__ __launch_bounds__(256) void wconv(const float* __restrict__ W, int widx)
{
    __shared__ float tile[32][33];
    __half* dst = g_w + (size_t)widx * MB1;
    const int tx = threadIdx.x & 31, ty0 = threadIdx.x >> 5;
    const int n0 = blockIdx.x * 32, k0 = blockIdx.y * 32;
#pragma unroll
    for (int r = ty0; r < 32; r += 8)
        tile[r][tx] = W[(size_t)(k0 + r) * Cc + n0 + tx];
    __syncthreads();
#pragma unroll
    for (int r = ty0; r < 32; r += 8)
        dst[(size_t)(n0 + r) * Cc + k0 + tx] = __float2half_rn(tile[tx][r]);
}

// ---------------- pipelined 2-term fp16 mma GEMM ----------------
// C = (Ahi + Alo) @ B_fp16 + bias. 128x128 tile, K-chunk 32, 3-stage cp.async.
#define G_MAT 10240              // 128 rows * 80B
#define G_STG 30720              // Ahi|Alo|B
#define G_SMEM (3*G_STG)         // 92160

__global__ __launch_bounds__(256) void mma_gemm(
    const float* __restrict__ bias0, const float* __restrict__ bias1,
    const float* __restrict__ bias2, float* __restrict__ outPlain, int mode)
{
    extern __shared__ __align__(16) char smem_raw[];
    const uint32_t sb = smem_u32(smem_raw);

    const int tid = threadIdx.x, lane = tid & 31, wid = tid >> 5;
    const int wm = wid >> 2, wn = wid & 3;
    const int g = lane >> 2, tq = lane & 3;
    const int m0 = blockIdx.y * 128, n_g = blockIdx.x * 128;

    const __half* Ahi = (mode == 0) ? g_ahi : g_chi;
    const __half* Alo = (mode == 0) ? g_alo : g_clo;
    const __half* Bw  = (mode == 0) ? g_w : (g_w + 3 * (size_t)MB1);

    const int lr = tid >> 1;
    const int ls = tid & 1;
    const size_t ga_row = (size_t)(m0 + lr) * Cc;
    const size_t gb_row = (size_t)(n_g + lr) * Cc;

    auto load_chunk = [&](int ch, int st) {
        const uint32_t base = sb + st * G_STG + lr * 80 + ls * 32;
        const int gc = ch * 32 + ls * 16;
#pragma unroll
        for (int j = 0; j < 2; j++) {
            cp16(base + 0 * G_MAT + j * 16, Ahi + ga_row + gc + j * 8);
            cp16(base + 1 * G_MAT + j * 16, Alo + ga_row + gc + j * 8);
            cp16(base + 2 * G_MAT + j * 16, Bw  + gb_row + gc + j * 8);
        }
    };

    float acc[4][4][4];
#pragma unroll
    for (int i = 0; i < 4; i++)
#pragma unroll
        for (int j = 0; j < 4; j++)
#pragma unroll
            for (int r = 0; r < 4; r++) acc[i][j][r] = 0.f;

    load_chunk(0, 0); CP_COMMIT();
    load_chunk(1, 1); CP_COMMIT();

    const int arow = lane & 15;
    const int acol = (lane >> 4) * 16;
    const int brow = (lane & 7) + ((lane >> 4) & 1) * 8;
    const int bcol = ((lane >> 3) & 1) * 16;

    for (int ch = 0; ch < 32; ch++) {
        CP_WAIT(1);
        __syncthreads();
        if (ch + 2 < 32) load_chunk(ch + 2, (ch + 2) % 3);
        CP_COMMIT();

        const uint32_t st = sb + (ch % 3) * G_STG;
#pragma unroll
        for (int ks = 0; ks < 2; ks++) {
            const int kb = ks * 32;
            uint32_t ahi[4][4], alo[4][4];
#pragma unroll
            for (int mt = 0; mt < 4; mt++) {
                const uint32_t ra = st + (uint32_t)(wm * 64 + mt * 16 + arow) * 80 + kb + acol;
                ldm4(ahi[mt], ra);
                ldm4(alo[mt], ra + G_MAT);
            }
#pragma unroll
            for (int p = 0; p < 2; p++) {
                const uint32_t rb = st + 2 * G_MAT +
                    (uint32_t)(wn * 32 + p * 16 + brow) * 80 + kb + bcol;
                uint32_t b4[4];
                ldm4(b4, rb);
#pragma unroll
                for (int e = 0; e < 2; e++) {
                    const int nt = p * 2 + e;
                    const uint32_t b2[2] = {b4[e * 2], b4[e * 2 + 1]};
#pragma unroll
                    for (int mt = 0; mt < 4; mt++) {
                        mma_f16(acc[mt][nt], ahi[mt], b2);
                        mma_f16(acc[mt][nt], alo[mt], b2);
                    }
                }
            }
        }
    }

    if (mode == 0) {
        const int which = n_g >> 10;
        const int nloc = n_g & 1023;
        const float* bias = (which == 0) ? bias0 : (which == 1) ? bias1 : bias2;
#pragma unroll
        for (int mt = 0; mt < 4; mt++) {
            const int r0 = m0 + wm * 64 + mt * 16 + g;
            const int r1 = r0 + 8;
            const int b0i = r0 >> 11, t0 = r0 & 2047;
            const int b1i = r1 >> 11, t1 = r1 & 2047;
#pragma unroll
            for (int nt = 0; nt < 4; nt++) {
                const int c = nloc + wn * 32 + nt * 8 + tq * 2;
                const int h = c >> 6, d = c & 63;
                const size_t i0 = (((size_t)(b0i * Hh + h)) * Tt + t0) * 64 + d;
                const size_t i1 = (((size_t)(b1i * Hh + h)) * Tt + t1) * 64 + d;
                float v00 = acc[mt][nt][0] + bias[c],   v01 = acc[mt][nt][1] + bias[c + 1];
                float v10 = acc[mt][nt][2] + bias[c],   v11 = acc[mt][nt][3] + bias[c + 1];
                if (which == 0) {
                    split_store_h(g_qhi, g_qlo, i0, v00 * 0.125f, v01 * 0.125f);
                    split_store_h(g_qhi, g_qlo, i1, v10 * 0.125f, v11 * 0.125f);
                } else {
                    __half* out = (which == 1) ? g_k : g_v;
                    __half2 a2; a2.x = __float2half_rn(v00); a2.y = __float2half_rn(v01);
                    __half2 b2; b2.x = __float2half_rn(v10); b2.y = __float2half_rn(v11);
                    *(__half2*)&out[i0] = a2;
                    *(__half2*)&out[i1] = b2;
                }
            }
        }
    } else {
#pragma unroll
        for (int mt = 0; mt < 4; mt++) {
            const int r0 = m0 + wm * 64 + mt * 16 + g;
            const int r1 = r0 + 8;
#pragma unroll
            for (int nt = 0; nt < 4; nt++) {
                const int c = n_g + wn * 32 + nt * 8 + tq * 2;
                float2 v0 = {acc[mt][nt][0] + bias0[c], acc[mt][nt][1] + bias0[c + 1]};
                float2 v1 = {acc[mt][nt][2] + bias0[c], acc[mt][nt][3] + bias0[c + 1]};
                *(float2*)&outPlain[(size_t)r0 * Cc + c] = v0;
                *(float2*)&outPlain[(size_t)r1 * Cc + c] = v1;
            }
        }
    }
}

// ---------------- pipelined 2-term fp16 flash attention ----------------
// 128 q rows/CTA. K,V single fp16 double-buffered. Q split, register-resident.
#define A_MAT 9216               // 64 rows * 144B
#define A_STG 18432              // K|V
#define A_Q   36864              // Q staging offset (hi at A_Q, lo at A_Q+18432)
#define A_SMEM 73728

__global__ __launch_bounds__(256) void attn_mma()
{
    extern __shared__ __align__(16) char smem_raw[];
    const uint32_t sb = smem_u32(smem_raw);

    const int bh = blockIdx.y;
    const int qb = (int)gridDim.x - 1 - (int)blockIdx.x;   // heavy tiles first
    const int tid = threadIdx.x, lane = tid & 31, wid = tid >> 5;
    const int g = lane >> 2, tq = lane & 3;

    const size_t hb = (size_t)bh * Tt * 64;
    const int nch = 2 * (qb + 1);

    const int lr = tid >> 2;              // 0..63
    const int ls = tid & 3;               // 32B quarter-row

    auto load_kv = [&](int kb, int st) {
        const uint32_t base = sb + st * A_STG + lr * 144 + ls * 32;
        const size_t gr = hb + (size_t)(kb * 64 + lr) * 64 + ls * 16;
#pragma unroll
        for (int j = 0; j < 2; j++) {
            cp16(base + j * 16,         g_k + gr + j * 8);
            cp16(base + A_MAT + j * 16, g_v + gr + j * 8);
        }
    };

    load_kv(0, 0); CP_COMMIT();

    // stage Q (hi/lo) then lift fragments to registers
    {
        const int qr = tid >> 1;
        const int qs = (tid & 1) * 32;
        const __half* ph = g_qhi + hb + (size_t)(qb * 128 + qr) * 64 + qs;
        const __half* pl = g_qlo + hb + (size_t)(qb * 128 + qr) * 64 + qs;
        char* dh = smem_raw + A_Q + qr * 144 + qs * 2;
        char* dl = smem_raw + A_Q + 18432 + qr * 144 + qs * 2;
#pragma unroll
        for (int i = 0; i < 4; i++) {
            *(uint4*)(dh + i * 16) = *(const uint4*)(ph + i * 8);
            *(uint4*)(dl + i * 16) = *(const uint4*)(pl + i * 8);
        }
    }
    __syncthreads();

    const int arow = lane & 15;
    const int acol = (lane >> 4) * 16;
    uint32_t qfh[4][4], qfl[4][4];
#pragma unroll
    for (int ks = 0; ks < 4; ks++) {
        const uint32_t qa = sb + A_Q + (uint32_t)(wid * 16 + arow) * 144 + ks * 32 + acol;
        ldm4(qfh[ks], qa);
        ldm4(qfl[ks], qa + 18432);
    }

    float m_i[2] = {-1e30f, -1e30f}, l_i[2] = {0.f, 0.f};
    float O[8][4];
#pragma unroll
    for (int nt = 0; nt < 8; nt++)
#pragma unroll
        for (int r = 0; r < 4; r++) O[nt][r] = 0.f;

    const int qrow0 = qb * 128 + wid * 16 + g;
    const int qrow1 = qrow0 + 8;

    const int brow = (lane & 7) + ((lane >> 4) & 1) * 8;
    const int bcol = ((lane >> 3) & 1) * 16;
    const int vrow = (lane & 7) + ((lane >> 3) & 1) * 8;
    const int vcol = ((lane >> 4) & 1) * 16;

    for (int kb = 0; kb < nch; kb++) {
        CP_WAIT(0);
        __syncthreads();
        if (kb + 1 < nch) load_kv(kb + 1, (kb + 1) & 1);
        CP_COMMIT();

        const uint32_t st = sb + (kb & 1) * A_STG;
        const bool active = (kb * 64) <= (qb * 128 + wid * 16 + 15);
        if (active) {
            float S[8][4];
#pragma unroll
            for (int nt = 0; nt < 8; nt++)
#pragma unroll
                for (int r = 0; r < 4; r++) S[nt][r] = 0.f;

            // S = (Qhi + Qlo) K^T
#pragma unroll
            for (int ks = 0; ks < 4; ks++) {
#pragma unroll
                for (int p = 0; p < 4; p++) {
                    const uint32_t rb = st + (uint32_t)(p * 16 + brow) * 144 + ks * 32 + bcol;
                    uint32_t k4[4];
                    ldm4(k4, rb);
#pragma unroll
                    for (int e = 0; e < 2; e++) {
                        const int nt = p * 2 + e;
                        const uint32_t b2[2] = {k4[e * 2], k4[e * 2 + 1]};
                        mma_f16(S[nt], qfh[ks], b2);
                        mma_f16(S[nt], qfl[ks], b2);
                    }
                }
            }

            // causal mask
            if (kb * 64 + 63 > qrow0) {
#pragma unroll
                for (int nt = 0; nt < 8; nt++) {
#pragma unroll
                    for (int j = 0; j < 2; j++) {
                        const int col = kb * 64 + nt * 8 + tq * 2 + j;
                        if (col > qrow0) S[nt][j]     = -1e30f;
                        if (col > qrow1) S[nt][2 + j] = -1e30f;
                    }
                }
            }

            // online softmax
            float mx0 = -1e30f, mx1 = -1e30f;
#pragma unroll
            for (int nt = 0; nt < 8; nt++) {
                mx0 = fmaxf(mx0, fmaxf(S[nt][0], S[nt][1]));
                mx1 = fmaxf(mx1, fmaxf(S[nt][2], S[nt][3]));
            }
            mx0 = fmaxf(mx0, __shfl_xor_sync(0xffffffffu, mx0, 1));
            mx0 = fmaxf(mx0, __shfl_xor_sync(0xffffffffu, mx0, 2));
            mx1 = fmaxf(mx1, __shfl_xor_sync(0xffffffffu, mx1, 1));
            mx1 = fmaxf(mx1, __shfl_xor_sync(0xffffffffu, mx1, 2));

            const float mn0 = fmaxf(m_i[0], mx0), mn1 = fmaxf(m_i[1], mx1);
            const float cr0 = __expf(m_i[0] - mn0), cr1 = __expf(m_i[1] - mn1);
            m_i[0] = mn0; m_i[1] = mn1;

            float s0 = 0.f, s1 = 0.f;
#pragma unroll
            for (int nt = 0; nt < 8; nt++) {
                S[nt][0] = __expf(S[nt][0] - mn0);
                S[nt][1] = __expf(S[nt][1] - mn0);
                S[nt][2] = __expf(S[nt][2] - mn1);
                S[nt][3] = __expf(S[nt][3] - mn1);
                s0 += S[nt][0] + S[nt][1];
                s1 += S[nt][2] + S[nt][3];
            }
            s0 += __shfl_xor_sync(0xffffffffu, s0, 1);
            s0 += __shfl_xor_sync(0xffffffffu, s0, 2);
            s1 += __shfl_xor_sync(0xffffffffu, s1, 1);
            s1 += __shfl_xor_sync(0xffffffffu, s1, 2);
            l_i[0] = l_i[0] * cr0 + s0;
            l_i[1] = l_i[1] * cr1 + s1;
#pragma unroll
            for (int nt = 0; nt < 8; nt++) {
                O[nt][0] *= cr0; O[nt][1] *= cr0;
                O[nt][2] *= cr1; O[nt][3] *= cr1;
            }

            // O += (Phi + Plo) V
#pragma unroll
            for (int ks = 0; ks < 4; ks++) {
                const int n0t = 2 * ks, n1t = 2 * ks + 1;
                uint32_t phi[4], plo[4];
                phi[0] = pack2h(S[n0t][0], S[n0t][1]);
                phi[1] = pack2h(S[n0t][2], S[n0t][3]);
                phi[2] = pack2h(S[n1t][0], S[n1t][1]);
                phi[3] = pack2h(S[n1t][2], S[n1t][3]);
                plo[0] = pack2h(hres(S[n0t][0]), hres(S[n0t][1]));
                plo[1] = pack2h(hres(S[n0t][2]), hres(S[n0t][3]));
                plo[2] = pack2h(hres(S[n1t][0]), hres(S[n1t][1]));
                plo[3] = pack2h(hres(S[n1t][2]), hres(S[n1t][3]));
#pragma unroll
                for (int p = 0; p < 4; p++) {
                    const uint32_t rv = st + A_MAT +
                        (uint32_t)(ks * 16 + vrow) * 144 + p * 32 + vcol;
                    uint32_t v4[4];
                    ldm4t(v4, rv);
#pragma unroll
                    for (int e = 0; e < 2; e++) {
                        const int nt = p * 2 + e;
                        const uint32_t b2[2] = {v4[e * 2], v4[e * 2 + 1]};
                        mma_f16(O[nt], phi, b2);
                        mma_f16(O[nt], plo, b2);
                    }
                }
            }
        }
    }

    // epilogue: split ctx store
    const float inv0 = 1.f / l_i[0], inv1 = 1.f / l_i[1];
    const int b = bh >> 4, h = bh & 15;
    const size_t r0 = ((size_t)b * Tt + (qb * 128 + wid * 16 + g)) * Cc;
    const size_t r1 = r0 + 8 * Cc;
#pragma unroll
    for (int nt = 0; nt < 8; nt++) {
        const int c = h * 64 + nt * 8 + tq * 2;
        split_store_h(g_chi, g_clo, r0 + c, O[nt][0] * inv0, O[nt][1] * inv0);
        split_store_h(g_chi, g_clo, r1 + c, O[nt][2] * inv1, O[nt][3] * inv1);
    }
}

// ---------------- launch ----------------
extern "C" void kernel_launch(void* const* d_in, const int* in_sizes, int n_in,
                              void* d_out, int out_size)
{
    (void)in_sizes; (void)n_in; (void)out_size;
    const float* hs = (const float*)d_in[0];
    const float* Wq = (const float*)d_in[2];
    const float* bq = (const float*)d_in[3];
    const float* Wk = (const float*)d_in[4];
    const float* bk = (const float*)d_in[5];
    const float* Wv = (const float*)d_in[6];
    const float* bv = (const float*)d_in[7];
    const float* Wo = (const float*)d_in[8];
    const float* bo = (const float*)d_in[9];

    cudaFuncSetAttribute(mma_gemm, cudaFuncAttributeMaxDynamicSharedMemorySize, G_SMEM);
    cudaFuncSetAttribute(attn_mma, cudaFuncAttributeMaxDynamicSharedMemorySize, A_SMEM);

    split_hs<<<4096, 256>>>(hs);
    wconv<<<dim3(32, 32), 256>>>(Wq, 0);
    wconv<<<dim3(32, 32), 256>>>(Wk, 1);
    wconv<<<dim3(32, 32), 256>>>(Wv, 2);
    wconv<<<dim3(32, 32), 256>>>(Wo, 3);

    mma_gemm<<<dim3(24, 32), 256, G_SMEM>>>(bq, bk, bv, nullptr, 0);
    attn_mma<<<dim3(16, 32), 256, A_SMEM>>>();
    mma_gemm<<<dim3(8, 32), 256, G_SMEM>>>(bo, nullptr, nullptr, (float*)d_out, 1);
}

// round 6
// speedup vs baseline: 4.3511x; 1.0845x over previous
#include <cuda_runtime.h>
#include <cuda_fp16.h>
#include <cstdint>

#define Tt 2048
#define Cc 1024
#define Hh 16
#define Mm 4096
#define MB1 (1024*1024)

// ---------------- static device scratch ----------------
__device__ __half g_ahi[Mm*Cc], g_alo[Mm*Cc];   // hidden_states split (fp16 hi/lo)
__device__ __half g_qhi[Mm*Cc], g_qlo[Mm*Cc];   // Q [B*H,T,64] split, pre-scaled
__device__ __half g_k[Mm*Cc];                   // K single fp16
__device__ __half g_v[Mm*Cc];                   // V single fp16
__device__ __half g_chi[Mm*Cc], g_clo[Mm*Cc];   // ctx split [M,C]
__device__ __half g_w[4*MB1];                   // Wq^T|Wk^T|Wv^T|Wo^T [N,K] fp16

// ---------------- helpers ----------------
__device__ __forceinline__ uint32_t smem_u32(const void* p) {
    uint32_t a;
    asm("{ .reg .u64 t; cvta.to.shared.u64 t, %1; cvt.u32.u64 %0, t; }" : "=r"(a) : "l"(p));
    return a;
}
__device__ __forceinline__ void mma_f16(float c[4], const uint32_t a[4], const uint32_t b[2]) {
    asm volatile(
        "mma.sync.aligned.m16n8k16.row.col.f32.f16.f16.f32 "
        "{%0,%1,%2,%3}, {%4,%5,%6,%7}, {%8,%9}, {%0,%1,%2,%3};"
        : "+f"(c[0]), "+f"(c[1]), "+f"(c[2]), "+f"(c[3])
        : "r"(a[0]), "r"(a[1]), "r"(a[2]), "r"(a[3]), "r"(b[0]), "r"(b[1]));
}
__device__ __forceinline__ void ldm4(uint32_t* r, uint32_t a) {
    asm volatile("ldmatrix.sync.aligned.m8n8.x4.shared.b16 {%0,%1,%2,%3}, [%4];"
        : "=r"(r[0]), "=r"(r[1]), "=r"(r[2]), "=r"(r[3]) : "r"(a));
}
__device__ __forceinline__ void ldm4t(uint32_t* r, uint32_t a) {
    asm volatile("ldmatrix.sync.aligned.m8n8.x4.trans.shared.b16 {%0,%1,%2,%3}, [%4];"
        : "=r"(r[0]), "=r"(r[1]), "=r"(r[2]), "=r"(r[3]) : "r"(a));
}
__device__ __forceinline__ void cp16(uint32_t d, const void* s) {
    asm volatile("cp.async.cg.shared.global [%0], [%1], 16;" :: "r"(d), "l"(s));
}
#define CP_COMMIT() asm volatile("cp.async.commit_group;" ::: "memory")
#define CP_WAIT(n)  asm volatile("cp.async.wait_group %0;" :: "n"(n) : "memory")

__device__ __forceinline__ uint32_t pack2h(float x, float y) {
    __half2 t;
    t.x = __float2half_rn(x);
    t.y = __float2half_rn(y);
    return *(uint32_t*)&t;
}
__device__ __forceinline__ void split_store_h(__half* hi, __half* lo,
                                              size_t idx, float a, float b) {
    __half ha = __float2half_rn(a), hb = __float2half_rn(b);
    __half2 hv; hv.x = ha; hv.y = hb;
    *(__half2*)&hi[idx] = hv;
    __half2 lv;
    lv.x = __float2half_rn(a - __half2float(ha));
    lv.y = __float2half_rn(b - __half2float(hb));
    *(__half2*)&lo[idx] = lv;
}

// ---------------- prep kernels ----------------
__global__ __launch_bounds__(256) void split_hs(const float* __restrict__ src)
{
    size_t i0 = ((size_t)blockIdx.x * 256 + threadIdx.x) * 4;
    float4 x = *(const float4*)(src + i0);
    float xs[4] = {x.x, x.y, x.z, x.w};
#pragma unroll
    for (int j = 0; j < 4; j++) {
        __half h = __float2half_rn(xs[j]);
        g_ahi[i0 + j] = h;
        g_alo[i0 + j] = __float2half_rn(xs[j] - __half2float(h));
    }
}

__global__ __launch_bounds__(256) void wconv4(
    const float* __restrict__ W0, const float* __restrict__ W1,
    const float* __restrict__ W2, const float* __restrict__ W3)
{
    __shared__ float tile[32][33];
    const int widx = blockIdx.z;
    const float* W = (widx == 0) ? W0 : (widx == 1) ? W1 : (widx == 2) ? W2 : W3;
    __half* dst = g_w + (size_t)widx * MB1;
    const int tx = threadIdx.x & 31, ty0 = threadIdx.x >> 5;
    const int n0 = blockIdx.x * 32, k0 = blockIdx.y * 32;
#pragma unroll
    for (int r = ty0; r < 32; r += 8)
        tile[r][tx] = W[(size_t)(k0 + r) * Cc + n0 + tx];
    __syncthreads();
#pragma unroll
    for (int r = ty0; r < 32; r += 8)
        dst[(size_t)(n0 + r) * Cc + k0 + tx] = __float2half_rn(tile[tx][r]);
}

// ---------------- pipelined 2-term fp16 mma GEMM ----------------
// C = (Ahi + Alo) @ B_fp16 + bias. 128x128 tile, K-chunk 32, 3-stage cp.async.
#define G_MAT 10240              // 128 rows * 80B
#define G_STG 30720              // Ahi|Alo|B
#define G_SMEM (3*G_STG)         // 92160

__global__ __launch_bounds__(256) void mma_gemm(
    const float* __restrict__ bias0, const float* __restrict__ bias1,
    const float* __restrict__ bias2, float* __restrict__ outPlain, int mode)
{
    extern __shared__ __align__(16) char smem_raw[];
    const uint32_t sb = smem_u32(smem_raw);

    const int tid = threadIdx.x, lane = tid & 31, wid = tid >> 5;
    const int wm = wid >> 2, wn = wid & 3;
    const int g = lane >> 2, tq = lane & 3;
    const int m0 = blockIdx.y * 128, n_g = blockIdx.x * 128;

    const __half* Ahi = (mode == 0) ? g_ahi : g_chi;
    const __half* Alo = (mode == 0) ? g_alo : g_clo;
    const __half* Bw  = (mode == 0) ? g_w : (g_w + 3 * (size_t)MB1);

    const int lr = tid >> 1;
    const int ls = tid & 1;
    const size_t ga_row = (size_t)(m0 + lr) * Cc;
    const size_t gb_row = (size_t)(n_g + lr) * Cc;

    auto load_chunk = [&](int ch, int st) {
        const uint32_t base = sb + st * G_STG + lr * 80 + ls * 32;
        const int gc = ch * 32 + ls * 16;
#pragma unroll
        for (int j = 0; j < 2; j++) {
            cp16(base + 0 * G_MAT + j * 16, Ahi + ga_row + gc + j * 8);
            cp16(base + 1 * G_MAT + j * 16, Alo + ga_row + gc + j * 8);
            cp16(base + 2 * G_MAT + j * 16, Bw  + gb_row + gc + j * 8);
        }
    };

    float acc[4][4][4];
#pragma unroll
    for (int i = 0; i < 4; i++)
#pragma unroll
        for (int j = 0; j < 4; j++)
#pragma unroll
            for (int r = 0; r < 4; r++) acc[i][j][r] = 0.f;

    load_chunk(0, 0); CP_COMMIT();
    load_chunk(1, 1); CP_COMMIT();

    const int arow = lane & 15;
    const int acol = (lane >> 4) * 16;
    const int brow = (lane & 7) + ((lane >> 4) & 1) * 8;
    const int bcol = ((lane >> 3) & 1) * 16;

    for (int ch = 0; ch < 32; ch++) {
        CP_WAIT(1);
        __syncthreads();
        if (ch + 2 < 32) load_chunk(ch + 2, (ch + 2) % 3);
        CP_COMMIT();

        const uint32_t st = sb + (ch % 3) * G_STG;
#pragma unroll
        for (int ks = 0; ks < 2; ks++) {
            const int kb = ks * 32;
            uint32_t ahi[4][4], alo[4][4];
#pragma unroll
            for (int mt = 0; mt < 4; mt++) {
                const uint32_t ra = st + (uint32_t)(wm * 64 + mt * 16 + arow) * 80 + kb + acol;
                ldm4(ahi[mt], ra);
                ldm4(alo[mt], ra + G_MAT);
            }
#pragma unroll
            for (int p = 0; p < 2; p++) {
                const uint32_t rb = st + 2 * G_MAT +
                    (uint32_t)(wn * 32 + p * 16 + brow) * 80 + kb + bcol;
                uint32_t b4[4];
                ldm4(b4, rb);
#pragma unroll
                for (int e = 0; e < 2; e++) {
                    const int nt = p * 2 + e;
                    const uint32_t b2[2] = {b4[e * 2], b4[e * 2 + 1]};
#pragma unroll
                    for (int mt = 0; mt < 4; mt++) {
                        mma_f16(acc[mt][nt], ahi[mt], b2);
                        mma_f16(acc[mt][nt], alo[mt], b2);
                    }
                }
            }
        }
    }

    if (mode == 0) {
        const int which = n_g >> 10;
        const int nloc = n_g & 1023;
        const float* bias = (which == 0) ? bias0 : (which == 1) ? bias1 : bias2;
#pragma unroll
        for (int mt = 0; mt < 4; mt++) {
            const int r0 = m0 + wm * 64 + mt * 16 + g;
            const int r1 = r0 + 8;
            const int b0i = r0 >> 11, t0 = r0 & 2047;
            const int b1i = r1 >> 11, t1 = r1 & 2047;
#pragma unroll
            for (int nt = 0; nt < 4; nt++) {
                const int c = nloc + wn * 32 + nt * 8 + tq * 2;
                const int h = c >> 6, d = c & 63;
                const size_t i0 = (((size_t)(b0i * Hh + h)) * Tt + t0) * 64 + d;
                const size_t i1 = (((size_t)(b1i * Hh + h)) * Tt + t1) * 64 + d;
                float v00 = acc[mt][nt][0] + bias[c],   v01 = acc[mt][nt][1] + bias[c + 1];
                float v10 = acc[mt][nt][2] + bias[c],   v11 = acc[mt][nt][3] + bias[c + 1];
                if (which == 0) {
                    split_store_h(g_qhi, g_qlo, i0, v00 * 0.125f, v01 * 0.125f);
                    split_store_h(g_qhi, g_qlo, i1, v10 * 0.125f, v11 * 0.125f);
                } else {
                    __half* out = (which == 1) ? g_k : g_v;
                    __half2 a2; a2.x = __float2half_rn(v00); a2.y = __float2half_rn(v01);
                    __half2 b2; b2.x = __float2half_rn(v10); b2.y = __float2half_rn(v11);
                    *(__half2*)&out[i0] = a2;
                    *(__half2*)&out[i1] = b2;
                }
            }
        }
    } else {
#pragma unroll
        for (int mt = 0; mt < 4; mt++) {
            const int r0 = m0 + wm * 64 + mt * 16 + g;
            const int r1 = r0 + 8;
#pragma unroll
            for (int nt = 0; nt < 4; nt++) {
                const int c = n_g + wn * 32 + nt * 8 + tq * 2;
                float2 v0 = {acc[mt][nt][0] + bias0[c], acc[mt][nt][1] + bias0[c + 1]};
                float2 v1 = {acc[mt][nt][2] + bias0[c], acc[mt][nt][3] + bias0[c + 1]};
                *(float2*)&outPlain[(size_t)r0 * Cc + c] = v0;
                *(float2*)&outPlain[(size_t)r1 * Cc + c] = v1;
            }
        }
    }
}

// ---------------- pipelined fp16 flash attention ----------------
// 128 q rows/CTA. K,V single fp16 double-buffered. Q split (2-term S),
// P single fp16 (1-term PV).
#define A_MAT 9216               // 64 rows * 144B
#define A_STG 18432              // K|V
#define A_Q   36864              // Q staging (hi at A_Q, lo at A_Q+18432)
#define A_SMEM 73728

__global__ __launch_bounds__(256) void attn_mma()
{
    extern __shared__ __align__(16) char smem_raw[];
    const uint32_t sb = smem_u32(smem_raw);

    const int bh = blockIdx.y;
    const int qb = (int)gridDim.x - 1 - (int)blockIdx.x;   // heavy tiles first
    const int tid = threadIdx.x, lane = tid & 31, wid = tid >> 5;
    const int g = lane >> 2, tq = lane & 3;

    const size_t hb = (size_t)bh * Tt * 64;
    const int nch = 2 * (qb + 1);

    const int lr = tid >> 2;
    const int ls = tid & 3;

    auto load_kv = [&](int kb, int st) {
        const uint32_t base = sb + st * A_STG + lr * 144 + ls * 32;
        const size_t gr = hb + (size_t)(kb * 64 + lr) * 64 + ls * 16;
#pragma unroll
        for (int j = 0; j < 2; j++) {
            cp16(base + j * 16,         g_k + gr + j * 8);
            cp16(base + A_MAT + j * 16, g_v + gr + j * 8);
        }
    };

    load_kv(0, 0); CP_COMMIT();

    // stage Q (hi/lo) then lift fragments to registers
    {
        const int qr = tid >> 1;
        const int qs = (tid & 1) * 32;
        const __half* ph = g_qhi + hb + (size_t)(qb * 128 + qr) * 64 + qs;
        const __half* pl = g_qlo + hb + (size_t)(qb * 128 + qr) * 64 + qs;
        char* dh = smem_raw + A_Q + qr * 144 + qs * 2;
        char* dl = smem_raw + A_Q + 18432 + qr * 144 + qs * 2;
#pragma unroll
        for (int i = 0; i < 4; i++) {
            *(uint4*)(dh + i * 16) = *(const uint4*)(ph + i * 8);
            *(uint4*)(dl + i * 16) = *(const uint4*)(pl + i * 8);
        }
    }
    __syncthreads();

    const int arow = lane & 15;
    const int acol = (lane >> 4) * 16;
    uint32_t qfh[4][4], qfl[4][4];
#pragma unroll
    for (int ks = 0; ks < 4; ks++) {
        const uint32_t qa = sb + A_Q + (uint32_t)(wid * 16 + arow) * 144 + ks * 32 + acol;
        ldm4(qfh[ks], qa);
        ldm4(qfl[ks], qa + 18432);
    }

    float m_i[2] = {-1e30f, -1e30f}, l_i[2] = {0.f, 0.f};
    float O[8][4];
#pragma unroll
    for (int nt = 0; nt < 8; nt++)
#pragma unroll
        for (int r = 0; r < 4; r++) O[nt][r] = 0.f;

    const int qrow0 = qb * 128 + wid * 16 + g;
    const int qrow1 = qrow0 + 8;

    const int brow = (lane & 7) + ((lane >> 4) & 1) * 8;
    const int bcol = ((lane >> 3) & 1) * 16;
    const int vrow = (lane & 7) + ((lane >> 3) & 1) * 8;
    const int vcol = ((lane >> 4) & 1) * 16;

    for (int kb = 0; kb < nch; kb++) {
        CP_WAIT(0);
        __syncthreads();
        if (kb + 1 < nch) load_kv(kb + 1, (kb + 1) & 1);
        CP_COMMIT();

        const uint32_t st = sb + (kb & 1) * A_STG;
        const bool active = (kb * 64) <= (qb * 128 + wid * 16 + 15);
        if (active) {
            float S[8][4];
#pragma unroll
            for (int nt = 0; nt < 8; nt++)
#pragma unroll
                for (int r = 0; r < 4; r++) S[nt][r] = 0.f;

            // S = (Qhi + Qlo) K^T
#pragma unroll
            for (int ks = 0; ks < 4; ks++) {
#pragma unroll
                for (int p = 0; p < 4; p++) {
                    const uint32_t rb = st + (uint32_t)(p * 16 + brow) * 144 + ks * 32 + bcol;
                    uint32_t k4[4];
                    ldm4(k4, rb);
#pragma unroll
                    for (int e = 0; e < 2; e++) {
                        const int nt = p * 2 + e;
                        const uint32_t b2[2] = {k4[e * 2], k4[e * 2 + 1]};
                        mma_f16(S[nt], qfh[ks], b2);
                        mma_f16(S[nt], qfl[ks], b2);
                    }
                }
            }

            // causal mask
            if (kb * 64 + 63 > qrow0) {
#pragma unroll
                for (int nt = 0; nt < 8; nt++) {
#pragma unroll
                    for (int j = 0; j < 2; j++) {
                        const int col = kb * 64 + nt * 8 + tq * 2 + j;
                        if (col > qrow0) S[nt][j]     = -1e30f;
                        if (col > qrow1) S[nt][2 + j] = -1e30f;
                    }
                }
            }

            // online softmax
            float mx0 = -1e30f, mx1 = -1e30f;
#pragma unroll
            for (int nt = 0; nt < 8; nt++) {
                mx0 = fmaxf(mx0, fmaxf(S[nt][0], S[nt][1]));
                mx1 = fmaxf(mx1, fmaxf(S[nt][2], S[nt][3]));
            }
            mx0 = fmaxf(mx0, __shfl_xor_sync(0xffffffffu, mx0, 1));
            mx0 = fmaxf(mx0, __shfl_xor_sync(0xffffffffu, mx0, 2));
            mx1 = fmaxf(mx1, __shfl_xor_sync(0xffffffffu, mx1, 1));
            mx1 = fmaxf(mx1, __shfl_xor_sync(0xffffffffu, mx1, 2));

            const float mn0 = fmaxf(m_i[0], mx0), mn1 = fmaxf(m_i[1], mx1);
            const float cr0 = __expf(m_i[0] - mn0), cr1 = __expf(m_i[1] - mn1);
            m_i[0] = mn0; m_i[1] = mn1;

            float s0 = 0.f, s1 = 0.f;
#pragma unroll
            for (int nt = 0; nt < 8; nt++) {
                S[nt][0] = __expf(S[nt][0] - mn0);
                S[nt][1] = __expf(S[nt][1] - mn0);
                S[nt][2] = __expf(S[nt][2] - mn1);
                S[nt][3] = __expf(S[nt][3] - mn1);
                s0 += S[nt][0] + S[nt][1];
                s1 += S[nt][2] + S[nt][3];
            }
            s0 += __shfl_xor_sync(0xffffffffu, s0, 1);
            s0 += __shfl_xor_sync(0xffffffffu, s0, 2);
            s1 += __shfl_xor_sync(0xffffffffu, s1, 1);
            s1 += __shfl_xor_sync(0xffffffffu, s1, 2);
            l_i[0] = l_i[0] * cr0 + s0;
            l_i[1] = l_i[1] * cr1 + s1;
#pragma unroll
            for (int nt = 0; nt < 8; nt++) {
                O[nt][0] *= cr0; O[nt][1] *= cr0;
                O[nt][2] *= cr1; O[nt][3] *= cr1;
            }

            // O += P V  (single-term fp16 P)
#pragma unroll
            for (int ks = 0; ks < 4; ks++) {
                const int n0t = 2 * ks, n1t = 2 * ks + 1;
                uint32_t phi[4];
                phi[0] = pack2h(S[n0t][0], S[n0t][1]);
                phi[1] = pack2h(S[n0t][2], S[n0t][3]);
                phi[2] = pack2h(S[n1t][0], S[n1t][1]);
                phi[3] = pack2h(S[n1t][2], S[n1t][3]);
#pragma unroll
                for (int p = 0; p < 4; p++) {
                    const uint32_t rv = st + A_MAT +
                        (uint32_t)(ks * 16 + vrow) * 144 + p * 32 + vcol;
                    uint32_t v4[4];
                    ldm4t(v4, rv);
#pragma unroll
                    for (int e = 0; e < 2; e++) {
                        const int nt = p * 2 + e;
                        const uint32_t b2[2] = {v4[e * 2], v4[e * 2 + 1]};
                        mma_f16(O[nt], phi, b2);
                    }
                }
            }
        }
    }

    // epilogue: split ctx store
    const float inv0 = 1.f / l_i[0], inv1 = 1.f / l_i[1];
    const int b = bh >> 4, h = bh & 15;
    const size_t r0 = ((size_t)b * Tt + (qb * 128 + wid * 16 + g)) * Cc;
    const size_t r1 = r0 + 8 * Cc;
#pragma unroll
    for (int nt = 0; nt < 8; nt++) {
        const int c = h * 64 + nt * 8 + tq * 2;
        split_store_h(g_chi, g_clo, r0 + c, O[nt][0] * inv0, O[nt][1] * inv0);
        split_store_h(g_chi, g_clo, r1 + c, O[nt][2] * inv1, O[nt][3] * inv1);
    }
}

// ---------------- launch ----------------
extern "C" void kernel_launch(void* const* d_in, const int* in_sizes, int n_in,
                              void* d_out, int out_size)
{
    (void)in_sizes; (void)n_in; (void)out_size;
    const float* hs = (const float*)d_in[0];
    const float* Wq = (const float*)d_in[2];
    const float* bq = (const float*)d_in[3];
    const float* Wk = (const float*)d_in[4];
    const float* bk = (const float*)d_in[5];
    const float* Wv = (const float*)d_in[6];
    const float* bv = (const float*)d_in[7];
    const float* Wo = (const float*)d_in[8];
    const float* bo = (const float*)d_in[9];

    cudaFuncSetAttribute(mma_gemm, cudaFuncAttributeMaxDynamicSharedMemorySize, G_SMEM);
    cudaFuncSetAttribute(attn_mma, cudaFuncAttributeMaxDynamicSharedMemorySize, A_SMEM);

    split_hs<<<4096, 256>>>(hs);
    wconv4<<<dim3(32, 32, 4), 256>>>(Wq, Wk, Wv, Wo);

    mma_gemm<<<dim3(24, 32), 256, G_SMEM>>>(bq, bk, bv, nullptr, 0);
    attn_mma<<<dim3(16, 32), 256, A_SMEM>>>();
    mma_gemm<<<dim3(8, 32), 256, G_SMEM>>>(bo, nullptr, nullptr, (float*)d_out, 1);
}

// round 7
// speedup vs baseline: 5.3520x; 1.2300x over previous
#include <cuda_runtime.h>
#include <cuda_fp16.h>
#include <cstdint>

#define Tt 2048
#define Cc 1024
#define Hh 16
#define Mm 4096
#define MB1 (1024*1024)

// ---------------- static device scratch ----------------
__device__ __half g_a[Mm*Cc];                   // hidden_states fp16
__device__ __half g_q[Mm*Cc];                   // Q [B*H,T,64] fp16, pre-scaled
__device__ __half g_k[Mm*Cc];                   // K fp16
__device__ __half g_v[Mm*Cc];                   // V fp16
__device__ __half g_chi[Mm*Cc], g_clo[Mm*Cc];   // ctx split [M,C] (kept 2-term)
__device__ __half g_w[4*MB1];                   // Wq^T|Wk^T|Wv^T|Wo^T [N,K] fp16

// ---------------- helpers ----------------
__device__ __forceinline__ uint32_t smem_u32(const void* p) {
    uint32_t a;
    asm("{ .reg .u64 t; cvta.to.shared.u64 t, %1; cvt.u32.u64 %0, t; }" : "=r"(a) : "l"(p));
    return a;
}
__device__ __forceinline__ void mma_f16(float c[4], const uint32_t a[4], const uint32_t b[2]) {
    asm volatile(
        "mma.sync.aligned.m16n8k16.row.col.f32.f16.f16.f32 "
        "{%0,%1,%2,%3}, {%4,%5,%6,%7}, {%8,%9}, {%0,%1,%2,%3};"
        : "+f"(c[0]), "+f"(c[1]), "+f"(c[2]), "+f"(c[3])
        : "r"(a[0]), "r"(a[1]), "r"(a[2]), "r"(a[3]), "r"(b[0]), "r"(b[1]));
}
__device__ __forceinline__ void ldm4(uint32_t* r, uint32_t a) {
    asm volatile("ldmatrix.sync.aligned.m8n8.x4.shared.b16 {%0,%1,%2,%3}, [%4];"
        : "=r"(r[0]), "=r"(r[1]), "=r"(r[2]), "=r"(r[3]) : "r"(a));
}
__device__ __forceinline__ void ldm4t(uint32_t* r, uint32_t a) {
    asm volatile("ldmatrix.sync.aligned.m8n8.x4.trans.shared.b16 {%0,%1,%2,%3}, [%4];"
        : "=r"(r[0]), "=r"(r[1]), "=r"(r[2]), "=r"(r[3]) : "r"(a));
}
__device__ __forceinline__ void cp16(uint32_t d, const void* s) {
    asm volatile("cp.async.cg.shared.global [%0], [%1], 16;" :: "r"(d), "l"(s));
}
#define CP_COMMIT() asm volatile("cp.async.commit_group;" ::: "memory")
#define CP_WAIT(n)  asm volatile("cp.async.wait_group %0;" :: "n"(n) : "memory")

__device__ __forceinline__ uint32_t pack2h(float x, float y) {
    __half2 t;
    t.x = __float2half_rn(x);
    t.y = __float2half_rn(y);
    return *(uint32_t*)&t;
}
__device__ __forceinline__ void split_store_h(__half* hi, __half* lo,
                                              size_t idx, float a, float b) {
    __half ha = __float2half_rn(a), hb = __float2half_rn(b);
    __half2 hv; hv.x = ha; hv.y = hb;
    *(__half2*)&hi[idx] = hv;
    __half2 lv;
    lv.x = __float2half_rn(a - __half2float(ha));
    lv.y = __float2half_rn(b - __half2float(hb));
    *(__half2*)&lo[idx] = lv;
}

// ---------------- prep kernels ----------------
__global__ __launch_bounds__(256) void conv_hs(const float* __restrict__ src)
{
    size_t i0 = ((size_t)blockIdx.x * 256 + threadIdx.x) * 4;
    float4 x = *(const float4*)(src + i0);
    __half2 a; a.x = __float2half_rn(x.x); a.y = __float2half_rn(x.y);
    __half2 b; b.x = __float2half_rn(x.z); b.y = __float2half_rn(x.w);
    *(__half2*)&g_a[i0]     = a;
    *(__half2*)&g_a[i0 + 2] = b;
}

__global__ __launch_bounds__(256) void wconv4(
    const float* __restrict__ W0, const float* __restrict__ W1,
    const float* __restrict__ W2, const float* __restrict__ W3)
{
    __shared__ float tile[32][33];
    const int widx = blockIdx.z;
    const float* W = (widx == 0) ? W0 : (widx == 1) ? W1 : (widx == 2) ? W2 : W3;
    __half* dst = g_w + (size_t)widx * MB1;
    const int tx = threadIdx.x & 31, ty0 = threadIdx.x >> 5;
    const int n0 = blockIdx.x * 32, k0 = blockIdx.y * 32;
#pragma unroll
    for (int r = ty0; r < 32; r += 8)
        tile[r][tx] = W[(size_t)(k0 + r) * Cc + n0 + tx];
    __syncthreads();
#pragma unroll
    for (int r = ty0; r < 32; r += 8)
        dst[(size_t)(n0 + r) * Cc + k0 + tx] = __float2half_rn(tile[tx][r]);
}

// ---------------- pipelined fp16 mma GEMM ----------------
// mode 0 (1-term): C = A_fp16 @ W + bias -> q/k/v fp16 scatter
// mode 1 (2-term): C = (Chi + Clo) @ Wo + bias -> fp32 d_out
#define G_MAT 10240              // 128 rows * 80B
#define G_STG 30720              // A(hi)|A(lo)|B   (lo slot unused in mode 0)
#define G_SMEM (3*G_STG)         // 92160

__global__ __launch_bounds__(256) void mma_gemm(
    const float* __restrict__ bias0, const float* __restrict__ bias1,
    const float* __restrict__ bias2, float* __restrict__ outPlain, int mode)
{
    extern __shared__ __align__(16) char smem_raw[];
    const uint32_t sb = smem_u32(smem_raw);

    const int tid = threadIdx.x, lane = tid & 31, wid = tid >> 5;
    const int wm = wid >> 2, wn = wid & 3;
    const int g = lane >> 2, tq = lane & 3;
    const int m0 = blockIdx.y * 128, n_g = blockIdx.x * 128;
    const bool two_term = (mode == 1);

    const __half* Ahi = (mode == 0) ? g_a : g_chi;
    const __half* Alo = g_clo;
    const __half* Bw  = (mode == 0) ? g_w : (g_w + 3 * (size_t)MB1);

    const int lr = tid >> 1;
    const int ls = tid & 1;
    const size_t ga_row = (size_t)(m0 + lr) * Cc;
    const size_t gb_row = (size_t)(n_g + lr) * Cc;

    auto load_chunk = [&](int ch, int st) {
        const uint32_t base = sb + st * G_STG + lr * 80 + ls * 32;
        const int gc = ch * 32 + ls * 16;
#pragma unroll
        for (int j = 0; j < 2; j++) {
            cp16(base + 0 * G_MAT + j * 16, Ahi + ga_row + gc + j * 8);
            if (two_term)
                cp16(base + 1 * G_MAT + j * 16, Alo + ga_row + gc + j * 8);
            cp16(base + 2 * G_MAT + j * 16, Bw  + gb_row + gc + j * 8);
        }
    };

    float acc[4][4][4];
#pragma unroll
    for (int i = 0; i < 4; i++)
#pragma unroll
        for (int j = 0; j < 4; j++)
#pragma unroll
            for (int r = 0; r < 4; r++) acc[i][j][r] = 0.f;

    load_chunk(0, 0); CP_COMMIT();
    load_chunk(1, 1); CP_COMMIT();

    const int arow = lane & 15;
    const int acol = (lane >> 4) * 16;
    const int brow = (lane & 7) + ((lane >> 4) & 1) * 8;
    const int bcol = ((lane >> 3) & 1) * 16;

    for (int ch = 0; ch < 32; ch++) {
        CP_WAIT(1);
        __syncthreads();
        if (ch + 2 < 32) load_chunk(ch + 2, (ch + 2) % 3);
        CP_COMMIT();

        const uint32_t st = sb + (ch % 3) * G_STG;
#pragma unroll
        for (int ks = 0; ks < 2; ks++) {
            const int kb = ks * 32;
            uint32_t ahi[4][4], alo[4][4];
#pragma unroll
            for (int mt = 0; mt < 4; mt++) {
                const uint32_t ra = st + (uint32_t)(wm * 64 + mt * 16 + arow) * 80 + kb + acol;
                ldm4(ahi[mt], ra);
                if (two_term) ldm4(alo[mt], ra + G_MAT);
            }
#pragma unroll
            for (int p = 0; p < 2; p++) {
                const uint32_t rb = st + 2 * G_MAT +
                    (uint32_t)(wn * 32 + p * 16 + brow) * 80 + kb + bcol;
                uint32_t b4[4];
                ldm4(b4, rb);
#pragma unroll
                for (int e = 0; e < 2; e++) {
                    const int nt = p * 2 + e;
                    const uint32_t b2[2] = {b4[e * 2], b4[e * 2 + 1]};
#pragma unroll
                    for (int mt = 0; mt < 4; mt++) {
                        mma_f16(acc[mt][nt], ahi[mt], b2);
                        if (two_term) mma_f16(acc[mt][nt], alo[mt], b2);
                    }
                }
            }
        }
    }

    if (mode == 0) {
        const int which = n_g >> 10;
        const int nloc = n_g & 1023;
        const float* bias = (which == 0) ? bias0 : (which == 1) ? bias1 : bias2;
        __half* out = (which == 0) ? g_q : (which == 1) ? g_k : g_v;
        const float scale = (which == 0) ? 0.125f : 1.0f;
#pragma unroll
        for (int mt = 0; mt < 4; mt++) {
            const int r0 = m0 + wm * 64 + mt * 16 + g;
            const int r1 = r0 + 8;
            const int b0i = r0 >> 11, t0 = r0 & 2047;
            const int b1i = r1 >> 11, t1 = r1 & 2047;
#pragma unroll
            for (int nt = 0; nt < 4; nt++) {
                const int c = nloc + wn * 32 + nt * 8 + tq * 2;
                const int h = c >> 6, d = c & 63;
                const size_t i0 = (((size_t)(b0i * Hh + h)) * Tt + t0) * 64 + d;
                const size_t i1 = (((size_t)(b1i * Hh + h)) * Tt + t1) * 64 + d;
                __half2 a2, b2;
                a2.x = __float2half_rn((acc[mt][nt][0] + bias[c])     * scale);
                a2.y = __float2half_rn((acc[mt][nt][1] + bias[c + 1]) * scale);
                b2.x = __float2half_rn((acc[mt][nt][2] + bias[c])     * scale);
                b2.y = __float2half_rn((acc[mt][nt][3] + bias[c + 1]) * scale);
                *(__half2*)&out[i0] = a2;
                *(__half2*)&out[i1] = b2;
            }
        }
    } else {
#pragma unroll
        for (int mt = 0; mt < 4; mt++) {
            const int r0 = m0 + wm * 64 + mt * 16 + g;
            const int r1 = r0 + 8;
#pragma unroll
            for (int nt = 0; nt < 4; nt++) {
                const int c = n_g + wn * 32 + nt * 8 + tq * 2;
                float2 v0 = {acc[mt][nt][0] + bias0[c], acc[mt][nt][1] + bias0[c + 1]};
                float2 v1 = {acc[mt][nt][2] + bias0[c], acc[mt][nt][3] + bias0[c + 1]};
                *(float2*)&outPlain[(size_t)r0 * Cc + c] = v0;
                *(float2*)&outPlain[(size_t)r1 * Cc + c] = v1;
            }
        }
    }
}

// ---------------- pipelined fp16 flash attention ----------------
// 128 q rows/CTA. K,V fp16 double-buffered; Q fragments loaded straight
// from gmem (no smem staging). S and PV single-term fp16.
#define A_MAT 9216               // 64 rows * 144B
#define A_STG 18432              // K|V
#define A_SMEM (2*A_STG)         // 36864

__global__ __launch_bounds__(256) void attn_mma()
{
    extern __shared__ __align__(16) char smem_raw[];
    const uint32_t sb = smem_u32(smem_raw);

    const int bh = blockIdx.y;
    const int qb = (int)gridDim.x - 1 - (int)blockIdx.x;   // heavy tiles first
    const int tid = threadIdx.x, lane = tid & 31, wid = tid >> 5;
    const int g = lane >> 2, tq = lane & 3;

    const size_t hb = (size_t)bh * Tt * 64;
    const int nch = 2 * (qb + 1);

    const int lr = tid >> 2;
    const int ls = tid & 3;

    auto load_kv = [&](int kb, int st) {
        const uint32_t base = sb + st * A_STG + lr * 144 + ls * 32;
        const size_t gr = hb + (size_t)(kb * 64 + lr) * 64 + ls * 16;
#pragma unroll
        for (int j = 0; j < 2; j++) {
            cp16(base + j * 16,         g_k + gr + j * 8);
            cp16(base + A_MAT + j * 16, g_v + gr + j * 8);
        }
    };

    load_kv(0, 0); CP_COMMIT();

    // Q fragments straight from global (row-major [t, d], d contiguous)
    uint32_t qf[4][4];
    {
        const __half* qp = g_q + hb + (size_t)(qb * 128 + wid * 16 + g) * 64;
#pragma unroll
        for (int ks = 0; ks < 4; ks++) {
            const int c = ks * 16 + tq * 2;
            qf[ks][0] = *(const uint32_t*)(qp + c);
            qf[ks][1] = *(const uint32_t*)(qp + 8 * 64 + c);
            qf[ks][2] = *(const uint32_t*)(qp + c + 8);
            qf[ks][3] = *(const uint32_t*)(qp + 8 * 64 + c + 8);
        }
    }

    float m_i[2] = {-1e30f, -1e30f}, l_i[2] = {0.f, 0.f};
    float O[8][4];
#pragma unroll
    for (int nt = 0; nt < 8; nt++)
#pragma unroll
        for (int r = 0; r < 4; r++) O[nt][r] = 0.f;

    const int qrow0 = qb * 128 + wid * 16 + g;
    const int qrow1 = qrow0 + 8;

    const int brow = (lane & 7) + ((lane >> 4) & 1) * 8;
    const int bcol = ((lane >> 3) & 1) * 16;
    const int vrow = (lane & 7) + ((lane >> 3) & 1) * 8;
    const int vcol = ((lane >> 4) & 1) * 16;

    for (int kb = 0; kb < nch; kb++) {
        CP_WAIT(0);
        __syncthreads();
        if (kb + 1 < nch) load_kv(kb + 1, (kb + 1) & 1);
        CP_COMMIT();

        const uint32_t st = sb + (kb & 1) * A_STG;
        const bool active = (kb * 64) <= (qb * 128 + wid * 16 + 15);
        if (active) {
            float S[8][4];
#pragma unroll
            for (int nt = 0; nt < 8; nt++)
#pragma unroll
                for (int r = 0; r < 4; r++) S[nt][r] = 0.f;

            // S = Q K^T (single-term)
#pragma unroll
            for (int ks = 0; ks < 4; ks++) {
#pragma unroll
                for (int p = 0; p < 4; p++) {
                    const uint32_t rb = st + (uint32_t)(p * 16 + brow) * 144 + ks * 32 + bcol;
                    uint32_t k4[4];
                    ldm4(k4, rb);
#pragma unroll
                    for (int e = 0; e < 2; e++) {
                        const int nt = p * 2 + e;
                        const uint32_t b2[2] = {k4[e * 2], k4[e * 2 + 1]};
                        mma_f16(S[nt], qf[ks], b2);
                    }
                }
            }

            // causal mask
            if (kb * 64 + 63 > qrow0) {
#pragma unroll
                for (int nt = 0; nt < 8; nt++) {
#pragma unroll
                    for (int j = 0; j < 2; j++) {
                        const int col = kb * 64 + nt * 8 + tq * 2 + j;
                        if (col > qrow0) S[nt][j]     = -1e30f;
                        if (col > qrow1) S[nt][2 + j] = -1e30f;
                    }
                }
            }

            // online softmax
            float mx0 = -1e30f, mx1 = -1e30f;
#pragma unroll
            for (int nt = 0; nt < 8; nt++) {
                mx0 = fmaxf(mx0, fmaxf(S[nt][0], S[nt][1]));
                mx1 = fmaxf(mx1, fmaxf(S[nt][2], S[nt][3]));
            }
            mx0 = fmaxf(mx0, __shfl_xor_sync(0xffffffffu, mx0, 1));
            mx0 = fmaxf(mx0, __shfl_xor_sync(0xffffffffu, mx0, 2));
            mx1 = fmaxf(mx1, __shfl_xor_sync(0xffffffffu, mx1, 1));
            mx1 = fmaxf(mx1, __shfl_xor_sync(0xffffffffu, mx1, 2));

            const float mn0 = fmaxf(m_i[0], mx0), mn1 = fmaxf(m_i[1], mx1);
            const float cr0 = __expf(m_i[0] - mn0), cr1 = __expf(m_i[1] - mn1);
            m_i[0] = mn0; m_i[1] = mn1;

            float s0 = 0.f, s1 = 0.f;
#pragma unroll
            for (int nt = 0; nt < 8; nt++) {
                S[nt][0] = __expf(S[nt][0] - mn0);
                S[nt][1] = __expf(S[nt][1] - mn0);
                S[nt][2] = __expf(S[nt][2] - mn1);
                S[nt][3] = __expf(S[nt][3] - mn1);
                s0 += S[nt][0] + S[nt][1];
                s1 += S[nt][2] + S[nt][3];
            }
            s0 += __shfl_xor_sync(0xffffffffu, s0, 1);
            s0 += __shfl_xor_sync(0xffffffffu, s0, 2);
            s1 += __shfl_xor_sync(0xffffffffu, s1, 1);
            s1 += __shfl_xor_sync(0xffffffffu, s1, 2);
            l_i[0] = l_i[0] * cr0 + s0;
            l_i[1] = l_i[1] * cr1 + s1;
#pragma unroll
            for (int nt = 0; nt < 8; nt++) {
                O[nt][0] *= cr0; O[nt][1] *= cr0;
                O[nt][2] *= cr1; O[nt][3] *= cr1;
            }

            // O += P V  (single-term fp16 P)
#pragma unroll
            for (int ks = 0; ks < 4; ks++) {
                const int n0t = 2 * ks, n1t = 2 * ks + 1;
                uint32_t phi[4];
                phi[0] = pack2h(S[n0t][0], S[n0t][1]);
                phi[1] = pack2h(S[n0t][2], S[n0t][3]);
                phi[2] = pack2h(S[n1t][0], S[n1t][1]);
                phi[3] = pack2h(S[n1t][2], S[n1t][3]);
#pragma unroll
                for (int p = 0; p < 4; p++) {
                    const uint32_t rv = st + A_MAT +
                        (uint32_t)(ks * 16 + vrow) * 144 + p * 32 + vcol;
                    uint32_t v4[4];
                    ldm4t(v4, rv);
#pragma unroll
                    for (int e = 0; e < 2; e++) {
                        const int nt = p * 2 + e;
                        const uint32_t b2[2] = {v4[e * 2], v4[e * 2 + 1]};
                        mma_f16(O[nt], phi, b2);
                    }
                }
            }
        }
    }

    // epilogue: split ctx store (2-term kept for out-proj accuracy)
    const float inv0 = 1.f / l_i[0], inv1 = 1.f / l_i[1];
    const int b = bh >> 4, h = bh & 15;
    const size_t r0 = ((size_t)b * Tt + (qb * 128 + wid * 16 + g)) * Cc;
    const size_t r1 = r0 + 8 * Cc;
#pragma unroll
    for (int nt = 0; nt < 8; nt++) {
        const int c = h * 64 + nt * 8 + tq * 2;
        split_store_h(g_chi, g_clo, r0 + c, O[nt][0] * inv0, O[nt][1] * inv0);
        split_store_h(g_chi, g_clo, r1 + c, O[nt][2] * inv1, O[nt][3] * inv1);
    }
}

// ---------------- launch ----------------
extern "C" void kernel_launch(void* const* d_in, const int* in_sizes, int n_in,
                              void* d_out, int out_size)
{
    (void)in_sizes; (void)n_in; (void)out_size;
    const float* hs = (const float*)d_in[0];
    const float* Wq = (const float*)d_in[2];
    const float* bq = (const float*)d_in[3];
    const float* Wk = (const float*)d_in[4];
    const float* bk = (const float*)d_in[5];
    const float* Wv = (const float*)d_in[6];
    const float* bv = (const float*)d_in[7];
    const float* Wo = (const float*)d_in[8];
    const float* bo = (const float*)d_in[9];

    cudaFuncSetAttribute(mma_gemm, cudaFuncAttributeMaxDynamicSharedMemorySize, G_SMEM);
    cudaFuncSetAttribute(attn_mma, cudaFuncAttributeMaxDynamicSharedMemorySize, A_SMEM);

    conv_hs<<<4096, 256>>>(hs);
    wconv4<<<dim3(32, 32, 4), 256>>>(Wq, Wk, Wv, Wo);

    mma_gemm<<<dim3(24, 32), 256, G_SMEM>>>(bq, bk, bv, nullptr, 0);
    attn_mma<<<dim3(16, 32), 256, A_SMEM>>>();
    mma_gemm<<<dim3(8, 32), 256, G_SMEM>>>(bo, nullptr, nullptr, (float*)d_out, 1);
}

// round 8
// speedup vs baseline: 6.6580x; 1.2440x over previous
#include <cuda_runtime.h>
#include <cuda_fp16.h>
#include <cstdint>

#define Tt 2048
#define Cc 1024
#define Hh 16
#define Mm 4096
#define MB1 (1024*1024)

// ---------------- static device scratch ----------------
__device__ __half g_a[Mm*Cc];                   // hidden_states fp16
__device__ __half g_q[Mm*Cc];                   // Q [B*H,T,64] fp16, pre-scaled
__device__ __half g_k[Mm*Cc];                   // K fp16
__device__ __half g_v[Mm*Cc];                   // V fp16
__device__ __half g_c[Mm*Cc];                   // ctx fp16 [M,C]
__device__ __half g_w[4*MB1];                   // Wq^T|Wk^T|Wv^T|Wo^T [N,K] fp16

// ---------------- helpers ----------------
__device__ __forceinline__ uint32_t smem_u32(const void* p) {
    uint32_t a;
    asm("{ .reg .u64 t; cvta.to.shared.u64 t, %1; cvt.u32.u64 %0, t; }" : "=r"(a) : "l"(p));
    return a;
}
__device__ __forceinline__ void mma_f16(float c[4], const uint32_t a[4], const uint32_t b[2]) {
    asm volatile(
        "mma.sync.aligned.m16n8k16.row.col.f32.f16.f16.f32 "
        "{%0,%1,%2,%3}, {%4,%5,%6,%7}, {%8,%9}, {%0,%1,%2,%3};"
        : "+f"(c[0]), "+f"(c[1]), "+f"(c[2]), "+f"(c[3])
        : "r"(a[0]), "r"(a[1]), "r"(a[2]), "r"(a[3]), "r"(b[0]), "r"(b[1]));
}
__device__ __forceinline__ void ldm4(uint32_t* r, uint32_t a) {
    asm volatile("ldmatrix.sync.aligned.m8n8.x4.shared.b16 {%0,%1,%2,%3}, [%4];"
        : "=r"(r[0]), "=r"(r[1]), "=r"(r[2]), "=r"(r[3]) : "r"(a));
}
__device__ __forceinline__ void ldm4t(uint32_t* r, uint32_t a) {
    asm volatile("ldmatrix.sync.aligned.m8n8.x4.trans.shared.b16 {%0,%1,%2,%3}, [%4];"
        : "=r"(r[0]), "=r"(r[1]), "=r"(r[2]), "=r"(r[3]) : "r"(a));
}
__device__ __forceinline__ void cp16(uint32_t d, const void* s) {
    asm volatile("cp.async.cg.shared.global [%0], [%1], 16;" :: "r"(d), "l"(s));
}
#define CP_COMMIT() asm volatile("cp.async.commit_group;" ::: "memory")
#define CP_WAIT(n)  asm volatile("cp.async.wait_group %0;" :: "n"(n) : "memory")

__device__ __forceinline__ uint32_t pack2h(float x, float y) {
    __half2 t;
    t.x = __float2half_rn(x);
    t.y = __float2half_rn(y);
    return *(uint32_t*)&t;
}
// exp2 of a packed f16x2 (inputs already in log2 domain, fp32 -> pack -> ex2)
__device__ __forceinline__ uint32_t ex2h2(float x, float y) {
    uint32_t h = pack2h(x, y);
    uint32_t r;
    asm volatile("ex2.approx.f16x2 %0, %1;" : "=r"(r) : "r"(h));
    return r;
}

// ---------------- prep kernels ----------------
__global__ __launch_bounds__(256) void conv_hs(const float* __restrict__ src)
{
    size_t i0 = ((size_t)blockIdx.x * 256 + threadIdx.x) * 4;
    float4 x = *(const float4*)(src + i0);
    __half2 a; a.x = __float2half_rn(x.x); a.y = __float2half_rn(x.y);
    __half2 b; b.x = __float2half_rn(x.z); b.y = __float2half_rn(x.w);
    *(__half2*)&g_a[i0]     = a;
    *(__half2*)&g_a[i0 + 2] = b;
}

__global__ __launch_bounds__(256) void wconv4(
    const float* __restrict__ W0, const float* __restrict__ W1,
    const float* __restrict__ W2, const float* __restrict__ W3)
{
    __shared__ float tile[32][33];
    const int widx = blockIdx.z;
    const float* W = (widx == 0) ? W0 : (widx == 1) ? W1 : (widx == 2) ? W2 : W3;
    __half* dst = g_w + (size_t)widx * MB1;
    const int tx = threadIdx.x & 31, ty0 = threadIdx.x >> 5;
    const int n0 = blockIdx.x * 32, k0 = blockIdx.y * 32;
#pragma unroll
    for (int r = ty0; r < 32; r += 8)
        tile[r][tx] = W[(size_t)(k0 + r) * Cc + n0 + tx];
    __syncthreads();
#pragma unroll
    for (int r = ty0; r < 32; r += 8)
        dst[(size_t)(n0 + r) * Cc + k0 + tx] = __float2half_rn(tile[tx][r]);
}

// ---------------- pipelined 1-term fp16 mma GEMM ----------------
// mode 0: C = hs_fp16 @ Wqkv + bias -> q/k/v fp16 scatter
// mode 1: C = ctx_fp16 @ Wo  + bias -> fp32 d_out
#define G_MAT 10240              // 128 rows * 80B
#define G_STG 20480              // A|B
#define G_SMEM (3*G_STG)         // 61440

__global__ __launch_bounds__(256) void mma_gemm(
    const float* __restrict__ bias0, const float* __restrict__ bias1,
    const float* __restrict__ bias2, float* __restrict__ outPlain, int mode)
{
    extern __shared__ __align__(16) char smem_raw[];
    const uint32_t sb = smem_u32(smem_raw);

    const int tid = threadIdx.x, lane = tid & 31, wid = tid >> 5;
    const int wm = wid >> 2, wn = wid & 3;
    const int g = lane >> 2, tq = lane & 3;
    const int m0 = blockIdx.y * 128, n_g = blockIdx.x * 128;

    const __half* Aa = (mode == 0) ? g_a : g_c;
    const __half* Bw = (mode == 0) ? g_w : (g_w + 3 * (size_t)MB1);

    const int lr = tid >> 1;
    const int ls = tid & 1;
    const size_t ga_row = (size_t)(m0 + lr) * Cc;
    const size_t gb_row = (size_t)(n_g + lr) * Cc;

    auto load_chunk = [&](int ch, int st) {
        const uint32_t base = sb + st * G_STG + lr * 80 + ls * 32;
        const int gc = ch * 32 + ls * 16;
#pragma unroll
        for (int j = 0; j < 2; j++) {
            cp16(base + j * 16,         Aa + ga_row + gc + j * 8);
            cp16(base + G_MAT + j * 16, Bw + gb_row + gc + j * 8);
        }
    };

    float acc[4][4][4];
#pragma unroll
    for (int i = 0; i < 4; i++)
#pragma unroll
        for (int j = 0; j < 4; j++)
#pragma unroll
            for (int r = 0; r < 4; r++) acc[i][j][r] = 0.f;

    load_chunk(0, 0); CP_COMMIT();
    load_chunk(1, 1); CP_COMMIT();

    const int arow = lane & 15;
    const int acol = (lane >> 4) * 16;
    const int brow = (lane & 7) + ((lane >> 4) & 1) * 8;
    const int bcol = ((lane >> 3) & 1) * 16;

    for (int ch = 0; ch < 32; ch++) {
        CP_WAIT(1);
        __syncthreads();
        if (ch + 2 < 32) load_chunk(ch + 2, (ch + 2) % 3);
        CP_COMMIT();

        const uint32_t st = sb + (ch % 3) * G_STG;
#pragma unroll
        for (int ks = 0; ks < 2; ks++) {
            const int kb = ks * 32;
            uint32_t af[4][4];
#pragma unroll
            for (int mt = 0; mt < 4; mt++) {
                const uint32_t ra = st + (uint32_t)(wm * 64 + mt * 16 + arow) * 80 + kb + acol;
                ldm4(af[mt], ra);
            }
#pragma unroll
            for (int p = 0; p < 2; p++) {
                const uint32_t rb = st + G_MAT +
                    (uint32_t)(wn * 32 + p * 16 + brow) * 80 + kb + bcol;
                uint32_t b4[4];
                ldm4(b4, rb);
#pragma unroll
                for (int e = 0; e < 2; e++) {
                    const int nt = p * 2 + e;
                    const uint32_t b2[2] = {b4[e * 2], b4[e * 2 + 1]};
#pragma unroll
                    for (int mt = 0; mt < 4; mt++)
                        mma_f16(acc[mt][nt], af[mt], b2);
                }
            }
        }
    }

    if (mode == 0) {
        const int which = n_g >> 10;
        const int nloc = n_g & 1023;
        const float* bias = (which == 0) ? bias0 : (which == 1) ? bias1 : bias2;
        __half* out = (which == 0) ? g_q : (which == 1) ? g_k : g_v;
        const float scale = (which == 0) ? 0.125f : 1.0f;
#pragma unroll
        for (int mt = 0; mt < 4; mt++) {
            const int r0 = m0 + wm * 64 + mt * 16 + g;
            const int r1 = r0 + 8;
            const int b0i = r0 >> 11, t0 = r0 & 2047;
            const int b1i = r1 >> 11, t1 = r1 & 2047;
#pragma unroll
            for (int nt = 0; nt < 4; nt++) {
                const int c = nloc + wn * 32 + nt * 8 + tq * 2;
                const int h = c >> 6, d = c & 63;
                const size_t i0 = (((size_t)(b0i * Hh + h)) * Tt + t0) * 64 + d;
                const size_t i1 = (((size_t)(b1i * Hh + h)) * Tt + t1) * 64 + d;
                __half2 a2, b2;
                a2.x = __float2half_rn((acc[mt][nt][0] + bias[c])     * scale);
                a2.y = __float2half_rn((acc[mt][nt][1] + bias[c + 1]) * scale);
                b2.x = __float2half_rn((acc[mt][nt][2] + bias[c])     * scale);
                b2.y = __float2half_rn((acc[mt][nt][3] + bias[c + 1]) * scale);
                *(__half2*)&out[i0] = a2;
                *(__half2*)&out[i1] = b2;
            }
        }
    } else {
#pragma unroll
        for (int mt = 0; mt < 4; mt++) {
            const int r0 = m0 + wm * 64 + mt * 16 + g;
            const int r1 = r0 + 8;
#pragma unroll
            for (int nt = 0; nt < 4; nt++) {
                const int c = n_g + wn * 32 + nt * 8 + tq * 2;
                float2 v0 = {acc[mt][nt][0] + bias0[c], acc[mt][nt][1] + bias0[c + 1]};
                float2 v1 = {acc[mt][nt][2] + bias0[c], acc[mt][nt][3] + bias0[c + 1]};
                *(float2*)&outPlain[(size_t)r0 * Cc + c] = v0;
                *(float2*)&outPlain[(size_t)r1 * Cc + c] = v1;
            }
        }
    }
}

// ---------------- pipelined fp16 flash attention ----------------
// 128 q rows/CTA. K,V fp16 double-buffered; Q fragments from gmem.
// Softmax exp via ex2.approx.f16x2 (P born packed-fp16 for PV).
#define A_MAT 9216               // 64 rows * 144B
#define A_STG 18432              // K|V
#define A_SMEM (2*A_STG)         // 36864

__global__ __launch_bounds__(256) void attn_mma()
{
    extern __shared__ __align__(16) char smem_raw[];
    const uint32_t sb = smem_u32(smem_raw);

    const int bh = blockIdx.y;
    const int qb = (int)gridDim.x - 1 - (int)blockIdx.x;   // heavy tiles first
    const int tid = threadIdx.x, lane = tid & 31, wid = tid >> 5;
    const int g = lane >> 2, tq = lane & 3;

    const size_t hb = (size_t)bh * Tt * 64;
    const int nch = 2 * (qb + 1);

    const int lr = tid >> 2;
    const int ls = tid & 3;

    auto load_kv = [&](int kb, int st) {
        const uint32_t base = sb + st * A_STG + lr * 144 + ls * 32;
        const size_t gr = hb + (size_t)(kb * 64 + lr) * 64 + ls * 16;
#pragma unroll
        for (int j = 0; j < 2; j++) {
            cp16(base + j * 16,         g_k + gr + j * 8);
            cp16(base + A_MAT + j * 16, g_v + gr + j * 8);
        }
    };

    load_kv(0, 0); CP_COMMIT();

    // Q fragments straight from global
    uint32_t qf[4][4];
    {
        const __half* qp = g_q + hb + (size_t)(qb * 128 + wid * 16 + g) * 64;
#pragma unroll
        for (int ks = 0; ks < 4; ks++) {
            const int c = ks * 16 + tq * 2;
            qf[ks][0] = *(const uint32_t*)(qp + c);
            qf[ks][1] = *(const uint32_t*)(qp + 8 * 64 + c);
            qf[ks][2] = *(const uint32_t*)(qp + c + 8);
            qf[ks][3] = *(const uint32_t*)(qp + 8 * 64 + c + 8);
        }
    }

    float m_i[2] = {-1e30f, -1e30f}, l_i[2] = {0.f, 0.f};
    float O[8][4];
#pragma unroll
    for (int nt = 0; nt < 8; nt++)
#pragma unroll
        for (int r = 0; r < 4; r++) O[nt][r] = 0.f;

    const int qrow0 = qb * 128 + wid * 16 + g;
    const int qrow1 = qrow0 + 8;

    const int brow = (lane & 7) + ((lane >> 4) & 1) * 8;
    const int bcol = ((lane >> 3) & 1) * 16;
    const int vrow = (lane & 7) + ((lane >> 3) & 1) * 8;
    const int vcol = ((lane >> 4) & 1) * 16;

    const float L2E = 1.4426950408889634f;

    for (int kb = 0; kb < nch; kb++) {
        CP_WAIT(0);
        __syncthreads();
        if (kb + 1 < nch) load_kv(kb + 1, (kb + 1) & 1);
        CP_COMMIT();

        const uint32_t st = sb + (kb & 1) * A_STG;
        const bool active = (kb * 64) <= (qb * 128 + wid * 16 + 15);
        if (active) {
            float S[8][4];
#pragma unroll
            for (int nt = 0; nt < 8; nt++)
#pragma unroll
                for (int r = 0; r < 4; r++) S[nt][r] = 0.f;

            // S = Q K^T
#pragma unroll
            for (int ks = 0; ks < 4; ks++) {
#pragma unroll
                for (int p = 0; p < 4; p++) {
                    const uint32_t rb = st + (uint32_t)(p * 16 + brow) * 144 + ks * 32 + bcol;
                    uint32_t k4[4];
                    ldm4(k4, rb);
#pragma unroll
                    for (int e = 0; e < 2; e++) {
                        const int nt = p * 2 + e;
                        const uint32_t b2[2] = {k4[e * 2], k4[e * 2 + 1]};
                        mma_f16(S[nt], qf[ks], b2);
                    }
                }
            }

            // causal mask
            if (kb * 64 + 63 > qrow0) {
#pragma unroll
                for (int nt = 0; nt < 8; nt++) {
#pragma unroll
                    for (int j = 0; j < 2; j++) {
                        const int col = kb * 64 + nt * 8 + tq * 2 + j;
                        if (col > qrow0) S[nt][j]     = -1e30f;
                        if (col > qrow1) S[nt][2 + j] = -1e30f;
                    }
                }
            }

            // online softmax (exp in packed fp16 via ex2.approx.f16x2)
            float mx0 = -1e30f, mx1 = -1e30f;
#pragma unroll
            for (int nt = 0; nt < 8; nt++) {
                mx0 = fmaxf(mx0, fmaxf(S[nt][0], S[nt][1]));
                mx1 = fmaxf(mx1, fmaxf(S[nt][2], S[nt][3]));
            }
            mx0 = fmaxf(mx0, __shfl_xor_sync(0xffffffffu, mx0, 1));
            mx0 = fmaxf(mx0, __shfl_xor_sync(0xffffffffu, mx0, 2));
            mx1 = fmaxf(mx1, __shfl_xor_sync(0xffffffffu, mx1, 1));
            mx1 = fmaxf(mx1, __shfl_xor_sync(0xffffffffu, mx1, 2));

            const float mn0 = fmaxf(m_i[0], mx0), mn1 = fmaxf(m_i[1], mx1);
            const float cr0 = __expf(m_i[0] - mn0), cr1 = __expf(m_i[1] - mn1);
            m_i[0] = mn0; m_i[1] = mn1;
            const float nm0 = -mn0 * L2E, nm1 = -mn1 * L2E;

            uint32_t P0[8], P1[8];
            float s0 = 0.f, s1 = 0.f;
#pragma unroll
            for (int nt = 0; nt < 8; nt++) {
                const uint32_t e0 = ex2h2(fmaf(S[nt][0], L2E, nm0),
                                          fmaf(S[nt][1], L2E, nm0));
                const uint32_t e1 = ex2h2(fmaf(S[nt][2], L2E, nm1),
                                          fmaf(S[nt][3], L2E, nm1));
                P0[nt] = e0; P1[nt] = e1;
                const float2 f0 = __half22float2(*(const __half2*)&e0);
                const float2 f1 = __half22float2(*(const __half2*)&e1);
                s0 += f0.x + f0.y;
                s1 += f1.x + f1.y;
            }
            s0 += __shfl_xor_sync(0xffffffffu, s0, 1);
            s0 += __shfl_xor_sync(0xffffffffu, s0, 2);
            s1 += __shfl_xor_sync(0xffffffffu, s1, 1);
            s1 += __shfl_xor_sync(0xffffffffu, s1, 2);
            l_i[0] = l_i[0] * cr0 + s0;
            l_i[1] = l_i[1] * cr1 + s1;
#pragma unroll
            for (int nt = 0; nt < 8; nt++) {
                O[nt][0] *= cr0; O[nt][1] *= cr0;
                O[nt][2] *= cr1; O[nt][3] *= cr1;
            }

            // O += P V (P already packed fp16)
#pragma unroll
            for (int ks = 0; ks < 4; ks++) {
                const uint32_t phi[4] = {P0[2 * ks], P1[2 * ks],
                                         P0[2 * ks + 1], P1[2 * ks + 1]};
#pragma unroll
                for (int p = 0; p < 4; p++) {
                    const uint32_t rv = st + A_MAT +
                        (uint32_t)(ks * 16 + vrow) * 144 + p * 32 + vcol;
                    uint32_t v4[4];
                    ldm4t(v4, rv);
#pragma unroll
                    for (int e = 0; e < 2; e++) {
                        const int nt = p * 2 + e;
                        const uint32_t b2[2] = {v4[e * 2], v4[e * 2 + 1]};
                        mma_f16(O[nt], phi, b2);
                    }
                }
            }
        }
    }

    // epilogue: plain fp16 ctx store
    const float inv0 = 1.f / l_i[0], inv1 = 1.f / l_i[1];
    const int b = bh >> 4, h = bh & 15;
    const size_t r0 = ((size_t)b * Tt + (qb * 128 + wid * 16 + g)) * Cc;
    const size_t r1 = r0 + 8 * Cc;
#pragma unroll
    for (int nt = 0; nt < 8; nt++) {
        const int c = h * 64 + nt * 8 + tq * 2;
        __half2 h0, h1;
        h0.x = __float2half_rn(O[nt][0] * inv0);
        h0.y = __float2half_rn(O[nt][1] * inv0);
        h1.x = __float2half_rn(O[nt][2] * inv1);
        h1.y = __float2half_rn(O[nt][3] * inv1);
        *(__half2*)&g_c[r0 + c] = h0;
        *(__half2*)&g_c[r1 + c] = h1;
    }
}

// ---------------- launch ----------------
extern "C" void kernel_launch(void* const* d_in, const int* in_sizes, int n_in,
                              void* d_out, int out_size)
{
    (void)in_sizes; (void)n_in; (void)out_size;
    const float* hs = (const float*)d_in[0];
    const float* Wq = (const float*)d_in[2];
    const float* bq = (const float*)d_in[3];
    const float* Wk = (const float*)d_in[4];
    const float* bk = (const float*)d_in[5];
    const float* Wv = (const float*)d_in[6];
    const float* bv = (const float*)d_in[7];
    const float* Wo = (const float*)d_in[8];
    const float* bo = (const float*)d_in[9];

    cudaFuncSetAttribute(mma_gemm, cudaFuncAttributeMaxDynamicSharedMemorySize, G_SMEM);
    cudaFuncSetAttribute(attn_mma, cudaFuncAttributeMaxDynamicSharedMemorySize, A_SMEM);

    conv_hs<<<4096, 256>>>(hs);
    wconv4<<<dim3(32, 32, 4), 256>>>(Wq, Wk, Wv, Wo);

    mma_gemm<<<dim3(24, 32), 256, G_SMEM>>>(bq, bk, bv, nullptr, 0);
    attn_mma<<<dim3(16, 32), 256, A_SMEM>>>();
    mma_gemm<<<dim3(8, 32), 256, G_SMEM>>>(bo, nullptr, nullptr, (float*)d_out, 1);
}